// round 6
// baseline (speedup 1.0000x reference)
#include <cuda_runtime.h>
#include <cuda_bf16.h>
#include <cstdint>
#include <math.h>

#define Dm   2048
#define Bb   4
#define Tt   2048
#define Hh   32
#define HSm  64
#define MROWS 8192
#define YSZ  (MROWS*Dm)
#define WSZ  (Dm*Dm)

typedef unsigned int u32;
typedef __nv_bfloat16 bf16;

// ---------------- static device scratch --------------------------------------
__device__ float g_k[YSZ], g_v[YSZ], g_u[YSZ], g_r[YSZ];
__device__ bf16  g_xnh[YSZ], g_xnl[YSZ], g_tph[YSZ], g_tpl[YSZ], g_oh[YSZ], g_ol[YSZ];
__device__ bf16  g_Wh[6][WSZ], g_Wl[6][WSZ];

// ---------------- helpers ------------------------------------------------------
#define CPA(dst,src)   asm volatile("cp.async.cg.shared.global [%0], [%1], 16;" :: "r"(dst), "l"(src))
#define CPCOMMIT()     asm volatile("cp.async.commit_group;" ::: "memory")
#define CPWAIT(n)      asm volatile("cp.async.wait_group %0;" :: "n"(n) : "memory")

__device__ __forceinline__ u32 s2u(const void* p){
    u32 a; asm("{ .reg .u64 t; cvta.to.shared.u64 t, %1; cvt.u32.u64 %0, t; }" : "=r"(a) : "l"(p)); return a;
}

__device__ __forceinline__ void mma16816(float* c, const u32* a, const u32* b){
    asm volatile("mma.sync.aligned.m16n8k16.row.col.f32.bf16.bf16.f32 "
        "{%0,%1,%2,%3}, {%4,%5,%6,%7}, {%8,%9}, {%0,%1,%2,%3};"
        : "+f"(c[0]), "+f"(c[1]), "+f"(c[2]), "+f"(c[3])
        : "r"(a[0]), "r"(a[1]), "r"(a[2]), "r"(a[3]), "r"(b[0]), "r"(b[1]));
}

#define LDSM4(r0,r1,r2,r3,addr) \
    asm volatile("ldmatrix.sync.aligned.m8n8.x4.shared.b16 {%0,%1,%2,%3}, [%4];" \
        : "=r"(r0), "=r"(r1), "=r"(r2), "=r"(r3) : "r"(addr))

union BF2U { __nv_bfloat162 h; u32 u; };

__device__ __forceinline__ void split4(float4 v, uint2& H, uint2& L){
    BF2U h0, h1, l0, l1;
    h0.h = __floats2bfloat162_rn(v.x, v.y);
    h1.h = __floats2bfloat162_rn(v.z, v.w);
    float lx = v.x - __bfloat162float(h0.h.x);
    float ly = v.y - __bfloat162float(h0.h.y);
    float lz = v.z - __bfloat162float(h1.h.x);
    float lw = v.w - __bfloat162float(h1.h.y);
    l0.h = __floats2bfloat162_rn(lx, ly);
    l1.h = __floats2bfloat162_rn(lz, lw);
    H.x = h0.u; H.y = h1.u; L.x = l0.u; L.y = l1.u;
}

// ---------------- weight split: fp32 -> (hi, lo) bf16 -------------------------
__global__ __launch_bounds__(256) void conv_hl(
    const float4* __restrict__ src, uint2* __restrict__ dh, uint2* __restrict__ dl)
{
    int i = blockIdx.x * 256 + threadIdx.x;
    float4 v = src[i];
    uint2 H, L;
    split4(v, H, L);
    dh[i] = H; dl[i] = L;
}

// ---------------- LayerNorm -> hi/lo bf16 -------------------------------------
__global__ __launch_bounds__(256) void ln_kernel(
    const float* __restrict__ x, const float* __restrict__ gam,
    const float* __restrict__ bet, bf16* __restrict__ oh, bf16* __restrict__ ol)
{
    __shared__ float red[18];
    const int row = blockIdx.x;
    const int t = threadIdx.x;
    const float* xr = x + (size_t)row * Dm;

    float4 a0 = *(const float4*)(xr + 4*t);
    float4 a1 = *(const float4*)(xr + 1024 + 4*t);
    float s  = a0.x+a0.y+a0.z+a0.w + a1.x+a1.y+a1.z+a1.w;
    float ss = a0.x*a0.x+a0.y*a0.y+a0.z*a0.z+a0.w*a0.w
             + a1.x*a1.x+a1.y*a1.y+a1.z*a1.z+a1.w*a1.w;
    #pragma unroll
    for (int o = 16; o; o >>= 1) {
        s  += __shfl_xor_sync(0xffffffffu, s,  o);
        ss += __shfl_xor_sync(0xffffffffu, ss, o);
    }
    if ((t & 31) == 0) { red[t>>5] = s; red[8 + (t>>5)] = ss; }
    __syncthreads();
    if (t == 0) {
        float S = 0.f, SS = 0.f;
        #pragma unroll
        for (int i = 0; i < 8; i++) { S += red[i]; SS += red[8+i]; }
        float mu  = S * (1.0f/Dm);
        float var = SS * (1.0f/Dm) - mu*mu;
        red[16] = mu;
        red[17] = rsqrtf(var + 1e-5f);
    }
    __syncthreads();
    const float mu = red[16], rstd = red[17];

    float4 g0 = *(const float4*)(gam + 4*t);
    float4 g1 = *(const float4*)(gam + 1024 + 4*t);
    float4 b0 = *(const float4*)(bet + 4*t);
    float4 b1 = *(const float4*)(bet + 1024 + 4*t);
    float4 r0, r1;
    r0.x = (a0.x - mu)*rstd*g0.x + b0.x;
    r0.y = (a0.y - mu)*rstd*g0.y + b0.y;
    r0.z = (a0.z - mu)*rstd*g0.z + b0.z;
    r0.w = (a0.w - mu)*rstd*g0.w + b0.w;
    r1.x = (a1.x - mu)*rstd*g1.x + b1.x;
    r1.y = (a1.y - mu)*rstd*g1.y + b1.y;
    r1.z = (a1.z - mu)*rstd*g1.z + b1.z;
    r1.w = (a1.w - mu)*rstd*g1.w + b1.w;

    uint2 H, L;
    const size_t o0 = (size_t)row * Dm + 4*t;
    split4(r0, H, L);
    *(uint2*)(oh + o0) = H; *(uint2*)(ol + o0) = L;
    split4(r1, H, L);
    *(uint2*)(oh + o0 + 1024) = H; *(uint2*)(ol + o0 + 1024) = L;
}

// ---------------- split-bf16 mma.sync GEMM: C = A @ W^T -----------------------
// CTA 128x128, BK=32, 8 warps (2x4), warp tile 64x32, double-buffered cp.async,
// ldmatrix fragment loads. smem rows padded to 80B -> conflict-free.

#define OFF(tile,buf) ((buf)*40960u + (tile)*10240u)   // AH=0 AL=1 BH=2 BL=3
#define SMEM_BYTES 81920

#define EPI_NONE 0
#define EPI_SIG  1
#define EPI_USIG 2
#define EPI_HL   3

__device__ __forceinline__ void load_tiles(
    u32 sb, int buf, int t,
    const bf16* Ah, const bf16* Al, const bf16* Bh, const bf16* Bl,
    size_t arow, size_t brow, int k0)
{
    #pragma unroll
    for (int p = 0; p < 2; p++) {
        int i = t + p*256;          // 0..511
        int r = i >> 2, c16 = i & 3;
        u32 dst = (u32)(r*80 + c16*16);
        size_t go = (size_t)r*Dm + k0 + c16*8;
        CPA(sb + OFF(0,buf) + dst, (const char*)(Ah + arow + go));
        CPA(sb + OFF(1,buf) + dst, (const char*)(Al + arow + go));
        CPA(sb + OFF(2,buf) + dst, (const char*)(Bh + brow + go));
        CPA(sb + OFF(3,buf) + dst, (const char*)(Bl + brow + go));
    }
}

template<int EPI>
__global__ __launch_bounds__(256, 2) void gemm_mma(
    const bf16* __restrict__ Ah, const bf16* __restrict__ Al,
    const bf16* __restrict__ Bh, const bf16* __restrict__ Bl,
    const float* __restrict__ bias,
    float* __restrict__ C, bf16* __restrict__ Ch, bf16* __restrict__ Cl)
{
    extern __shared__ char sm[];
    const u32 sb = s2u(sm);
    const int t = threadIdx.x;
    const int w = t >> 5, lane = t & 31;
    const int wm = w >> 2, wn = w & 3;       // warp grid 2 (m) x 4 (n)
    const int bn = blockIdx.x, bm = blockIdx.y;

    const size_t arow = (size_t)bm * 128 * Dm;
    const size_t brow = (size_t)bn * 128 * Dm;

    float acc[4][4][4];
    #pragma unroll
    for (int i = 0; i < 4; i++)
        #pragma unroll
        for (int j = 0; j < 4; j++)
            #pragma unroll
            for (int q = 0; q < 4; q++) acc[i][j][q] = 0.f;

    load_tiles(sb, 0, t, Ah, Al, Bh, Bl, arow, brow, 0);
    CPCOMMIT();

    // ldmatrix lane addressing
    const u32 l15 = lane & 15;
    const u32 lh16 = ((lane >> 4) & 1) * 16;
    const u32 aRowOff = (u32)(wm*64 + l15) * 80 + lh16;
    const u32 bRowOff = (u32)(wn*32 + l15) * 80 + lh16;

    for (int c = 0; c < 64; c++) {
        const int buf = c & 1;
        if (c + 1 < 64) {
            load_tiles(sb, buf ^ 1, t, Ah, Al, Bh, Bl, arow, brow, (c+1)*32);
            CPCOMMIT();
            CPWAIT(1);
        } else {
            CPWAIT(0);
        }
        __syncthreads();

        const u32 aH = sb + OFF(0,buf) + aRowOff;
        const u32 aL = sb + OFF(1,buf) + aRowOff;
        const u32 bH = sb + OFF(2,buf) + bRowOff;
        const u32 bL = sb + OFF(3,buf) + bRowOff;

        #pragma unroll
        for (int ks = 0; ks < 2; ks++) {
            const u32 ko = ks * 32;
            u32 ah[4][4], al[4][4], bh[4][2], bl[4][2];
            #pragma unroll
            for (int mt = 0; mt < 4; mt++) {
                LDSM4(ah[mt][0], ah[mt][1], ah[mt][2], ah[mt][3], aH + mt*1280u + ko);
                LDSM4(al[mt][0], al[mt][1], al[mt][2], al[mt][3], aL + mt*1280u + ko);
            }
            #pragma unroll
            for (int ng = 0; ng < 2; ng++) {
                u32 h0,h1,h2,h3, L0,L1,L2,L3;
                LDSM4(h0,h1,h2,h3, bH + ng*1280u + ko);
                LDSM4(L0,L1,L2,L3, bL + ng*1280u + ko);
                bh[2*ng+0][0] = h0; bh[2*ng+0][1] = h2;
                bh[2*ng+1][0] = h1; bh[2*ng+1][1] = h3;
                bl[2*ng+0][0] = L0; bl[2*ng+0][1] = L2;
                bl[2*ng+1][0] = L1; bl[2*ng+1][1] = L3;
            }
            #pragma unroll
            for (int mt = 0; mt < 4; mt++)
                #pragma unroll
                for (int nt = 0; nt < 4; nt++) {
                    mma16816(acc[mt][nt], ah[mt], bh[nt]);
                    mma16816(acc[mt][nt], ah[mt], bl[nt]);
                    mma16816(acc[mt][nt], al[mt], bh[nt]);
                }
        }
        __syncthreads();
    }

    // ---------------- epilogue ----------------
    const int lq = lane >> 2;
    const int lr = lane & 3;
    #pragma unroll
    for (int mt = 0; mt < 4; mt++) {
        #pragma unroll
        for (int nt = 0; nt < 4; nt++) {
            int row0 = bm*128 + wm*64 + mt*16 + lq;
            int col  = bn*128 + wn*32 + nt*8 + lr*2;
            float v0 = acc[mt][nt][0], v1 = acc[mt][nt][1];
            float v2 = acc[mt][nt][2], v3 = acc[mt][nt][3];
            if (EPI == EPI_SIG) {
                v0 = 1.0f/(1.0f+expf(-v0)); v1 = 1.0f/(1.0f+expf(-v1));
                v2 = 1.0f/(1.0f+expf(-v2)); v3 = 1.0f/(1.0f+expf(-v3));
            }
            if (EPI == EPI_USIG) {
                float bb0 = __ldg(bias + col), bb1 = __ldg(bias + col + 1);
                v0 = 1.0f/(1.0f+expf(v0+bb0)); v1 = 1.0f/(1.0f+expf(v1+bb1));
                v2 = 1.0f/(1.0f+expf(v2+bb0)); v3 = 1.0f/(1.0f+expf(v3+bb1));
            }
            if (EPI == EPI_HL) {
                BF2U H0, H1, L0, L1;
                H0.h = __floats2bfloat162_rn(v0, v1);
                H1.h = __floats2bfloat162_rn(v2, v3);
                L0.h = __floats2bfloat162_rn(v0 - __bfloat162float(H0.h.x),
                                             v1 - __bfloat162float(H0.h.y));
                L1.h = __floats2bfloat162_rn(v2 - __bfloat162float(H1.h.x),
                                             v3 - __bfloat162float(H1.h.y));
                *(u32*)(Ch + (size_t)row0*Dm + col)     = H0.u;
                *(u32*)(Ch + (size_t)(row0+8)*Dm + col) = H1.u;
                *(u32*)(Cl + (size_t)row0*Dm + col)     = L0.u;
                *(u32*)(Cl + (size_t)(row0+8)*Dm + col) = L1.u;
            } else {
                *(float2*)(C + (size_t)row0*Dm + col)     = make_float2(v0, v1);
                *(float2*)(C + (size_t)(row0+8)*Dm + col) = make_float2(v2, v3);
            }
        }
    }
}

// ---------------- selective-WKV recurrent scan --------------------------------
#define CH 8
__global__ __launch_bounds__(256) void scan_kernel(
    const float* __restrict__ kA, const float* __restrict__ vA,
    const float* __restrict__ uA, const float* __restrict__ rA,
    const float* __restrict__ state0, bf16* __restrict__ oh, bf16* __restrict__ ol,
    float* __restrict__ stateF)
{
    const int bh = blockIdx.x;
    const int b  = bh >> 5;
    const int h  = bh & 31;
    const size_t base = (size_t)b * Tt * Dm + (size_t)h * HSm;

    const int t  = threadIdx.x;
    const int ti = t >> 4;
    const int tj = t & 15;

    __shared__ float stg[4][CH][64];
    __shared__ float pS[CH][16][64];

    float S[4][4];
    const float* st0 = state0 + (size_t)bh * 4096;
    #pragma unroll
    for (int ii = 0; ii < 4; ii++) {
        float4 s4 = *(const float4*)(st0 + (ti*4+ii)*64 + tj*4);
        S[ii][0]=s4.x; S[ii][1]=s4.y; S[ii][2]=s4.z; S[ii][3]=s4.w;
    }

    const float* bases[4] = { kA + base, vA + base, uA + base, rA + base };

    for (int c = 0; c < Tt/CH; c++) {
        const size_t coff = (size_t)c * CH * Dm;
        #pragma unroll
        for (int p = 0; p < (4*CH*64)/256; p++) {
            int g = t + p*256;
            int s = g >> 8;
            int a = (g >> 6) & 3;
            int e = g & 63;
            stg[a][s][e] = bases[a][coff + (size_t)s*Dm + e];
        }
        __syncthreads();

        #pragma unroll
        for (int s = 0; s < CH; s++) {
            float4 k4 = *(const float4*)(&stg[0][s][ti*4]);
            float4 v4 = *(const float4*)(&stg[1][s][tj*4]);
            float4 u4 = *(const float4*)(&stg[2][s][ti*4]);
            float4 r4 = *(const float4*)(&stg[3][s][ti*4]);
            float kv[4] = {k4.x,k4.y,k4.z,k4.w};
            float uv[4] = {u4.x,u4.y,u4.z,u4.w};
            float rv[4] = {r4.x,r4.y,r4.z,r4.w};
            float vv[4] = {v4.x,v4.y,v4.z,v4.w};
            float p0=0.f,p1=0.f,p2=0.f,p3=0.f;
            #pragma unroll
            for (int ii = 0; ii < 4; ii++) {
                S[ii][0] = fmaf(uv[ii], S[ii][0], kv[ii]*vv[0]);
                S[ii][1] = fmaf(uv[ii], S[ii][1], kv[ii]*vv[1]);
                S[ii][2] = fmaf(uv[ii], S[ii][2], kv[ii]*vv[2]);
                S[ii][3] = fmaf(uv[ii], S[ii][3], kv[ii]*vv[3]);
                p0 = fmaf(rv[ii], S[ii][0], p0);
                p1 = fmaf(rv[ii], S[ii][1], p1);
                p2 = fmaf(rv[ii], S[ii][2], p2);
                p3 = fmaf(rv[ii], S[ii][3], p3);
            }
            *(float4*)(&pS[s][ti][tj*4]) = make_float4(p0,p1,p2,p3);
        }
        __syncthreads();

        #pragma unroll
        for (int q = 0; q < 2; q++) {
            int o = t + q*256;
            int s = o >> 6;
            int j = o & 63;
            float sum = 0.f;
            #pragma unroll
            for (int ii = 0; ii < 16; ii++) sum += pS[s][ii][j];
            size_t idx = base + coff + (size_t)s*Dm + j;
            bf16 hv = __float2bfloat16(sum);
            oh[idx] = hv;
            ol[idx] = __float2bfloat16(sum - __bfloat162float(hv));
        }
        __syncthreads();
    }

    float* sf = stateF + (size_t)bh * 4096;
    #pragma unroll
    for (int ii = 0; ii < 4; ii++)
        *(float4*)(sf + (ti*4+ii)*64 + tj*4)
            = make_float4(S[ii][0],S[ii][1],S[ii][2],S[ii][3]);
}

// ---------------- launch ------------------------------------------------------
extern "C" void kernel_launch(void* const* d_in, const int* in_sizes, int n_in,
                              void* d_out, int out_size)
{
    const float* x     = (const float*)d_in[0];
    const float* state = (const float*)d_in[1];
    const float* ln_g  = (const float*)d_in[2];
    const float* ln_b  = (const float*)d_in[3];
    const float* Wsrc[6] = {
        (const float*)d_in[4],   // Wx
        (const float*)d_in[5],   // Ww
        (const float*)d_in[7],   // Wk
        (const float*)d_in[8],   // Wv
        (const float*)d_in[9],   // Wr
        (const float*)d_in[10],  // Wo
    };
    const float* bw = (const float*)d_in[6];

    float* y_out  = (float*)d_out;
    float* sf_out = (float*)d_out + YSZ;

    float *kk, *vv, *uu, *rr;
    bf16 *xnh, *xnl, *tph, *tpl, *oh, *ol;
    bf16 *wh[6], *wl[6];
    cudaGetSymbolAddress((void**)&kk,  g_k);
    cudaGetSymbolAddress((void**)&vv,  g_v);
    cudaGetSymbolAddress((void**)&uu,  g_u);
    cudaGetSymbolAddress((void**)&rr,  g_r);
    cudaGetSymbolAddress((void**)&xnh, g_xnh);
    cudaGetSymbolAddress((void**)&xnl, g_xnl);
    cudaGetSymbolAddress((void**)&tph, g_tph);
    cudaGetSymbolAddress((void**)&tpl, g_tpl);
    cudaGetSymbolAddress((void**)&oh,  g_oh);
    cudaGetSymbolAddress((void**)&ol,  g_ol);
    {
        bf16 *bh, *bl;
        cudaGetSymbolAddress((void**)&bh, g_Wh);
        cudaGetSymbolAddress((void**)&bl, g_Wl);
        for (int i = 0; i < 6; i++) { wh[i] = bh + (size_t)i*WSZ; wl[i] = bl + (size_t)i*WSZ; }
    }

    cudaFuncSetAttribute(gemm_mma<EPI_NONE>, cudaFuncAttributeMaxDynamicSharedMemorySize, SMEM_BYTES);
    cudaFuncSetAttribute(gemm_mma<EPI_SIG>,  cudaFuncAttributeMaxDynamicSharedMemorySize, SMEM_BYTES);
    cudaFuncSetAttribute(gemm_mma<EPI_USIG>, cudaFuncAttributeMaxDynamicSharedMemorySize, SMEM_BYTES);
    cudaFuncSetAttribute(gemm_mma<EPI_HL>,   cudaFuncAttributeMaxDynamicSharedMemorySize, SMEM_BYTES);

    for (int i = 0; i < 6; i++)
        conv_hl<<<WSZ/1024, 256>>>((const float4*)Wsrc[i], (uint2*)wh[i], (uint2*)wl[i]);

    ln_kernel<<<MROWS, 256>>>(x, ln_g, ln_b, xnh, xnl);

    dim3 gg(Dm/128, MROWS/128);   // (16, 64)
    gemm_mma<EPI_HL><<<gg, 256, SMEM_BYTES>>>(xnh, xnl, wh[0], wl[0], nullptr, nullptr, tph, tpl);
    gemm_mma<EPI_USIG><<<gg, 256, SMEM_BYTES>>>(tph, tpl, wh[1], wl[1], bw, uu, nullptr, nullptr);
    gemm_mma<EPI_NONE><<<gg, 256, SMEM_BYTES>>>(xnh, xnl, wh[2], wl[2], nullptr, kk, nullptr, nullptr);
    gemm_mma<EPI_NONE><<<gg, 256, SMEM_BYTES>>>(xnh, xnl, wh[3], wl[3], nullptr, vv, nullptr, nullptr);
    gemm_mma<EPI_SIG><<<gg, 256, SMEM_BYTES>>>(xnh, xnl, wh[4], wl[4], nullptr, rr, nullptr, nullptr);
    scan_kernel<<<Bb*Hh, 256>>>(kk, vv, uu, rr, state, oh, ol, sf_out);
    gemm_mma<EPI_NONE><<<gg, 256, SMEM_BYTES>>>(oh, ol, wh[5], wl[5], nullptr, y_out, nullptr, nullptr);
}

// round 7
// speedup vs baseline: 1.6181x; 1.6181x over previous
#include <cuda_runtime.h>
#include <cuda_bf16.h>
#include <cstdint>
#include <math.h>

#define Dm   2048
#define Bb   4
#define Tt   2048
#define Hh   32
#define HSm  64
#define MROWS 8192
#define YSZ  (MROWS*Dm)
#define WSZ  (Dm*Dm)

typedef unsigned int u32;
typedef __nv_bfloat16 bf16;

// ---------------- static device scratch --------------------------------------
__device__ float g_k[YSZ], g_v[YSZ], g_u[YSZ], g_r[YSZ];
__device__ bf16  g_xnh[YSZ], g_xnl[YSZ], g_tph[YSZ], g_tpl[YSZ], g_oh[YSZ], g_ol[YSZ];
__device__ bf16  g_Wh[6][WSZ], g_Wl[6][WSZ];

// ---------------- helpers ------------------------------------------------------
#define CPA(dst,src)   asm volatile("cp.async.cg.shared.global [%0], [%1], 16;" :: "r"(dst), "l"(src))
#define CPCOMMIT()     asm volatile("cp.async.commit_group;" ::: "memory")
#define CPWAIT(n)      asm volatile("cp.async.wait_group %0;" :: "n"(n) : "memory")

__device__ __forceinline__ u32 s2u(const void* p){
    u32 a; asm("{ .reg .u64 t; cvta.to.shared.u64 t, %1; cvt.u32.u64 %0, t; }" : "=r"(a) : "l"(p)); return a;
}

__device__ __forceinline__ void mma16816(float* c, const u32* a, const u32* b){
    asm volatile("mma.sync.aligned.m16n8k16.row.col.f32.bf16.bf16.f32 "
        "{%0,%1,%2,%3}, {%4,%5,%6,%7}, {%8,%9}, {%0,%1,%2,%3};"
        : "+f"(c[0]), "+f"(c[1]), "+f"(c[2]), "+f"(c[3])
        : "r"(a[0]), "r"(a[1]), "r"(a[2]), "r"(a[3]), "r"(b[0]), "r"(b[1]));
}

union BF2U { __nv_bfloat162 h; u32 u; };

__device__ __forceinline__ void split4(float4 v, uint2& H, uint2& L){
    BF2U h0, h1, l0, l1;
    h0.h = __floats2bfloat162_rn(v.x, v.y);
    h1.h = __floats2bfloat162_rn(v.z, v.w);
    float lx = v.x - __bfloat162float(h0.h.x);
    float ly = v.y - __bfloat162float(h0.h.y);
    float lz = v.z - __bfloat162float(h1.h.x);
    float lw = v.w - __bfloat162float(h1.h.y);
    l0.h = __floats2bfloat162_rn(lx, ly);
    l1.h = __floats2bfloat162_rn(lz, lw);
    H.x = h0.u; H.y = h1.u; L.x = l0.u; L.y = l1.u;
}

// ---------------- weight split (ALL 6 weights in ONE launch) ------------------
__global__ __launch_bounds__(256) void conv_hl_all(
    const float4* __restrict__ s0, const float4* __restrict__ s1,
    const float4* __restrict__ s2, const float4* __restrict__ s3,
    const float4* __restrict__ s4, const float4* __restrict__ s5,
    uint2* __restrict__ dh, uint2* __restrict__ dl)
{
    const int wi = blockIdx.y;              // which weight
    const float4* src = wi==0?s0 : wi==1?s1 : wi==2?s2 : wi==3?s3 : wi==4?s4 : s5;
    int i = blockIdx.x * 256 + threadIdx.x;
    float4 v = src[i];
    uint2 H, L;
    split4(v, H, L);
    size_t o = (size_t)wi * (WSZ/4) + i;
    dh[o] = H; dl[o] = L;
}

// ---------------- LayerNorm -> hi/lo bf16 -------------------------------------
__global__ __launch_bounds__(256) void ln_kernel(
    const float* __restrict__ x, const float* __restrict__ gam,
    const float* __restrict__ bet, bf16* __restrict__ oh, bf16* __restrict__ ol)
{
    __shared__ float red[18];
    const int row = blockIdx.x;
    const int t = threadIdx.x;
    const float* xr = x + (size_t)row * Dm;

    float4 a0 = *(const float4*)(xr + 4*t);
    float4 a1 = *(const float4*)(xr + 1024 + 4*t);
    float s  = a0.x+a0.y+a0.z+a0.w + a1.x+a1.y+a1.z+a1.w;
    float ss = a0.x*a0.x+a0.y*a0.y+a0.z*a0.z+a0.w*a0.w
             + a1.x*a1.x+a1.y*a1.y+a1.z*a1.z+a1.w*a1.w;
    #pragma unroll
    for (int o = 16; o; o >>= 1) {
        s  += __shfl_xor_sync(0xffffffffu, s,  o);
        ss += __shfl_xor_sync(0xffffffffu, ss, o);
    }
    if ((t & 31) == 0) { red[t>>5] = s; red[8 + (t>>5)] = ss; }
    __syncthreads();
    if (t == 0) {
        float S = 0.f, SS = 0.f;
        #pragma unroll
        for (int i = 0; i < 8; i++) { S += red[i]; SS += red[8+i]; }
        float mu  = S * (1.0f/Dm);
        float var = SS * (1.0f/Dm) - mu*mu;
        red[16] = mu;
        red[17] = rsqrtf(var + 1e-5f);
    }
    __syncthreads();
    const float mu = red[16], rstd = red[17];

    float4 g0 = *(const float4*)(gam + 4*t);
    float4 g1 = *(const float4*)(gam + 1024 + 4*t);
    float4 b0 = *(const float4*)(bet + 4*t);
    float4 b1 = *(const float4*)(bet + 1024 + 4*t);
    float4 r0, r1;
    r0.x = (a0.x - mu)*rstd*g0.x + b0.x;
    r0.y = (a0.y - mu)*rstd*g0.y + b0.y;
    r0.z = (a0.z - mu)*rstd*g0.z + b0.z;
    r0.w = (a0.w - mu)*rstd*g0.w + b0.w;
    r1.x = (a1.x - mu)*rstd*g1.x + b1.x;
    r1.y = (a1.y - mu)*rstd*g1.y + b1.y;
    r1.z = (a1.z - mu)*rstd*g1.z + b1.z;
    r1.w = (a1.w - mu)*rstd*g1.w + b1.w;

    uint2 H, L;
    const size_t o0 = (size_t)row * Dm + 4*t;
    split4(r0, H, L);
    *(uint2*)(oh + o0) = H; *(uint2*)(ol + o0) = L;
    split4(r1, H, L);
    *(uint2*)(oh + o0 + 1024) = H; *(uint2*)(ol + o0 + 1024) = L;
}

// ---------------- split-bf16 mma.sync GEMM: C = A @ W^T -----------------------
// CTA 128x128, BK=32, 8 warps (2x4), warp tile 64x32, double-buffered cp.async.
// smem rows padded to 80B (40 bf16) -> conflict-free fragment loads.
// (EXACT Round-4 structure — fastest measured config.)

#define OFF(tile,buf) ((buf)*40960u + (tile)*10240u)   // AH=0 AL=1 BH=2 BL=3
#define SMEM_BYTES 81920

#define EPI_NONE 0
#define EPI_SIG  1
#define EPI_USIG 2
#define EPI_HL   3

__device__ __forceinline__ void load_tiles(
    u32 sb, int buf, int t,
    const bf16* Ah, const bf16* Al, const bf16* Bh, const bf16* Bl,
    size_t arow, size_t brow, int k0)
{
    #pragma unroll
    for (int p = 0; p < 2; p++) {
        int i = t + p*256;          // 0..511
        int r = i >> 2, c16 = i & 3;
        u32 dst = (u32)(r*80 + c16*16);
        size_t go = (size_t)r*Dm + k0 + c16*8;
        CPA(sb + OFF(0,buf) + dst, (const char*)(Ah + arow + go));
        CPA(sb + OFF(1,buf) + dst, (const char*)(Al + arow + go));
        CPA(sb + OFF(2,buf) + dst, (const char*)(Bh + brow + go));
        CPA(sb + OFF(3,buf) + dst, (const char*)(Bl + brow + go));
    }
}

template<int EPI>
__global__ __launch_bounds__(256) void gemm_mma(
    const bf16* __restrict__ Ah, const bf16* __restrict__ Al,
    const bf16* __restrict__ Bh, const bf16* __restrict__ Bl,
    const float* __restrict__ bias,
    float* __restrict__ C, bf16* __restrict__ Ch, bf16* __restrict__ Cl)
{
    extern __shared__ char sm[];
    const u32 sb = s2u(sm);
    const int t = threadIdx.x;
    const int w = t >> 5, lane = t & 31;
    const int wm = w >> 2, wn = w & 3;       // warp grid 2 (m) x 4 (n)
    const int bn = blockIdx.x, bm = blockIdx.y;

    const size_t arow = (size_t)bm * 128 * Dm;
    const size_t brow = (size_t)bn * 128 * Dm;

    float acc[4][4][4];
    #pragma unroll
    for (int i = 0; i < 4; i++)
        #pragma unroll
        for (int j = 0; j < 4; j++)
            #pragma unroll
            for (int q = 0; q < 4; q++) acc[i][j][q] = 0.f;

    load_tiles(sb, 0, t, Ah, Al, Bh, Bl, arow, brow, 0);
    CPCOMMIT();

    const int lq = lane >> 2;        // 0..7
    const int lr = lane & 3;         // 0..3

    for (int c = 0; c < 64; c++) {
        const int buf = c & 1;
        if (c + 1 < 64) {
            load_tiles(sb, buf ^ 1, t, Ah, Al, Bh, Bl, arow, brow, (c+1)*32);
            CPCOMMIT();
            CPWAIT(1);
        } else {
            CPWAIT(0);
        }
        __syncthreads();

        const bf16* sAh = (const bf16*)(sm + OFF(0,buf));
        const bf16* sAl = (const bf16*)(sm + OFF(1,buf));
        const bf16* sBh = (const bf16*)(sm + OFF(2,buf));
        const bf16* sBl = (const bf16*)(sm + OFF(3,buf));

        #pragma unroll
        for (int ks = 0; ks < 2; ks++) {
            const int kofs = ks*16 + lr*2;
            u32 ah[4][4], al[4][4], bh[4][2], bl[4][2];
            #pragma unroll
            for (int mt = 0; mt < 4; mt++) {
                int r0 = wm*64 + mt*16 + lq;
                ah[mt][0] = *(const u32*)(sAh + r0*40 + kofs);
                ah[mt][1] = *(const u32*)(sAh + (r0+8)*40 + kofs);
                ah[mt][2] = *(const u32*)(sAh + r0*40 + kofs + 8);
                ah[mt][3] = *(const u32*)(sAh + (r0+8)*40 + kofs + 8);
                al[mt][0] = *(const u32*)(sAl + r0*40 + kofs);
                al[mt][1] = *(const u32*)(sAl + (r0+8)*40 + kofs);
                al[mt][2] = *(const u32*)(sAl + r0*40 + kofs + 8);
                al[mt][3] = *(const u32*)(sAl + (r0+8)*40 + kofs + 8);
            }
            #pragma unroll
            for (int nt = 0; nt < 4; nt++) {
                int n0 = wn*32 + nt*8 + lq;
                bh[nt][0] = *(const u32*)(sBh + n0*40 + kofs);
                bh[nt][1] = *(const u32*)(sBh + n0*40 + kofs + 8);
                bl[nt][0] = *(const u32*)(sBl + n0*40 + kofs);
                bl[nt][1] = *(const u32*)(sBl + n0*40 + kofs + 8);
            }
            #pragma unroll
            for (int mt = 0; mt < 4; mt++)
                #pragma unroll
                for (int nt = 0; nt < 4; nt++) {
                    mma16816(acc[mt][nt], ah[mt], bh[nt]);
                    mma16816(acc[mt][nt], ah[mt], bl[nt]);
                    mma16816(acc[mt][nt], al[mt], bh[nt]);
                }
        }
        __syncthreads();
    }

    // ---------------- epilogue ----------------
    #pragma unroll
    for (int mt = 0; mt < 4; mt++) {
        #pragma unroll
        for (int nt = 0; nt < 4; nt++) {
            int row0 = bm*128 + wm*64 + mt*16 + lq;
            int col  = bn*128 + wn*32 + nt*8 + lr*2;
            float v0 = acc[mt][nt][0], v1 = acc[mt][nt][1];
            float v2 = acc[mt][nt][2], v3 = acc[mt][nt][3];
            if (EPI == EPI_SIG) {
                v0 = 1.0f/(1.0f+__expf(-v0)); v1 = 1.0f/(1.0f+__expf(-v1));
                v2 = 1.0f/(1.0f+__expf(-v2)); v3 = 1.0f/(1.0f+__expf(-v3));
            }
            if (EPI == EPI_USIG) {
                float bb0 = __ldg(bias + col), bb1 = __ldg(bias + col + 1);
                v0 = 1.0f/(1.0f+__expf(v0+bb0)); v1 = 1.0f/(1.0f+__expf(v1+bb1));
                v2 = 1.0f/(1.0f+__expf(v2+bb0)); v3 = 1.0f/(1.0f+__expf(v3+bb1));
            }
            if (EPI == EPI_HL) {
                BF2U H0, H1, L0, L1;
                H0.h = __floats2bfloat162_rn(v0, v1);
                H1.h = __floats2bfloat162_rn(v2, v3);
                L0.h = __floats2bfloat162_rn(v0 - __bfloat162float(H0.h.x),
                                             v1 - __bfloat162float(H0.h.y));
                L1.h = __floats2bfloat162_rn(v2 - __bfloat162float(H1.h.x),
                                             v3 - __bfloat162float(H1.h.y));
                *(u32*)(Ch + (size_t)row0*Dm + col)     = H0.u;
                *(u32*)(Ch + (size_t)(row0+8)*Dm + col) = H1.u;
                *(u32*)(Cl + (size_t)row0*Dm + col)     = L0.u;
                *(u32*)(Cl + (size_t)(row0+8)*Dm + col) = L1.u;
            } else {
                *(float2*)(C + (size_t)row0*Dm + col)     = make_float2(v0, v1);
                *(float2*)(C + (size_t)(row0+8)*Dm + col) = make_float2(v2, v3);
            }
        }
    }
}

// ---------------- selective-WKV recurrent scan --------------------------------
#define CH 8
__global__ __launch_bounds__(256) void scan_kernel(
    const float* __restrict__ kA, const float* __restrict__ vA,
    const float* __restrict__ uA, const float* __restrict__ rA,
    const float* __restrict__ state0, bf16* __restrict__ oh, bf16* __restrict__ ol,
    float* __restrict__ stateF)
{
    const int bh = blockIdx.x;
    const int b  = bh >> 5;
    const int h  = bh & 31;
    const size_t base = (size_t)b * Tt * Dm + (size_t)h * HSm;

    const int t  = threadIdx.x;
    const int ti = t >> 4;
    const int tj = t & 15;

    __shared__ float stg[4][CH][64];
    __shared__ float pS[CH][16][64];

    float S[4][4];
    const float* st0 = state0 + (size_t)bh * 4096;
    #pragma unroll
    for (int ii = 0; ii < 4; ii++) {
        float4 s4 = *(const float4*)(st0 + (ti*4+ii)*64 + tj*4);
        S[ii][0]=s4.x; S[ii][1]=s4.y; S[ii][2]=s4.z; S[ii][3]=s4.w;
    }

    const float* bases[4] = { kA + base, vA + base, uA + base, rA + base };

    for (int c = 0; c < Tt/CH; c++) {
        const size_t coff = (size_t)c * CH * Dm;
        #pragma unroll
        for (int p = 0; p < (4*CH*64)/256; p++) {
            int g = t + p*256;
            int s = g >> 8;
            int a = (g >> 6) & 3;
            int e = g & 63;
            stg[a][s][e] = bases[a][coff + (size_t)s*Dm + e];
        }
        __syncthreads();

        #pragma unroll
        for (int s = 0; s < CH; s++) {
            float4 k4 = *(const float4*)(&stg[0][s][ti*4]);
            float4 v4 = *(const float4*)(&stg[1][s][tj*4]);
            float4 u4 = *(const float4*)(&stg[2][s][ti*4]);
            float4 r4 = *(const float4*)(&stg[3][s][ti*4]);
            float kv[4] = {k4.x,k4.y,k4.z,k4.w};
            float uv[4] = {u4.x,u4.y,u4.z,u4.w};
            float rv[4] = {r4.x,r4.y,r4.z,r4.w};
            float vv[4] = {v4.x,v4.y,v4.z,v4.w};
            float p0=0.f,p1=0.f,p2=0.f,p3=0.f;
            #pragma unroll
            for (int ii = 0; ii < 4; ii++) {
                S[ii][0] = fmaf(uv[ii], S[ii][0], kv[ii]*vv[0]);
                S[ii][1] = fmaf(uv[ii], S[ii][1], kv[ii]*vv[1]);
                S[ii][2] = fmaf(uv[ii], S[ii][2], kv[ii]*vv[2]);
                S[ii][3] = fmaf(uv[ii], S[ii][3], kv[ii]*vv[3]);
                p0 = fmaf(rv[ii], S[ii][0], p0);
                p1 = fmaf(rv[ii], S[ii][1], p1);
                p2 = fmaf(rv[ii], S[ii][2], p2);
                p3 = fmaf(rv[ii], S[ii][3], p3);
            }
            *(float4*)(&pS[s][ti][tj*4]) = make_float4(p0,p1,p2,p3);
        }
        __syncthreads();

        #pragma unroll
        for (int q = 0; q < 2; q++) {
            int o = t + q*256;
            int s = o >> 6;
            int j = o & 63;
            float sum = 0.f;
            #pragma unroll
            for (int ii = 0; ii < 16; ii++) sum += pS[s][ii][j];
            size_t idx = base + coff + (size_t)s*Dm + j;
            bf16 hv = __float2bfloat16(sum);
            oh[idx] = hv;
            ol[idx] = __float2bfloat16(sum - __bfloat162float(hv));
        }
        __syncthreads();
    }

    float* sf = stateF + (size_t)bh * 4096;
    #pragma unroll
    for (int ii = 0; ii < 4; ii++)
        *(float4*)(sf + (ti*4+ii)*64 + tj*4)
            = make_float4(S[ii][0],S[ii][1],S[ii][2],S[ii][3]);
}

// ---------------- launch ------------------------------------------------------
extern "C" void kernel_launch(void* const* d_in, const int* in_sizes, int n_in,
                              void* d_out, int out_size)
{
    const float* x     = (const float*)d_in[0];
    const float* state = (const float*)d_in[1];
    const float* ln_g  = (const float*)d_in[2];
    const float* ln_b  = (const float*)d_in[3];
    const float* Wx    = (const float*)d_in[4];
    const float* Ww    = (const float*)d_in[5];
    const float* bw    = (const float*)d_in[6];
    const float* Wk    = (const float*)d_in[7];
    const float* Wv    = (const float*)d_in[8];
    const float* Wr    = (const float*)d_in[9];
    const float* Wo    = (const float*)d_in[10];

    float* y_out  = (float*)d_out;
    float* sf_out = (float*)d_out + YSZ;

    float *kk, *vv, *uu, *rr;
    bf16 *xnh, *xnl, *tph, *tpl, *oh, *ol;
    bf16 *wh[6], *wl[6];
    bf16 *whbase, *wlbase;
    cudaGetSymbolAddress((void**)&kk,  g_k);
    cudaGetSymbolAddress((void**)&vv,  g_v);
    cudaGetSymbolAddress((void**)&uu,  g_u);
    cudaGetSymbolAddress((void**)&rr,  g_r);
    cudaGetSymbolAddress((void**)&xnh, g_xnh);
    cudaGetSymbolAddress((void**)&xnl, g_xnl);
    cudaGetSymbolAddress((void**)&tph, g_tph);
    cudaGetSymbolAddress((void**)&tpl, g_tpl);
    cudaGetSymbolAddress((void**)&oh,  g_oh);
    cudaGetSymbolAddress((void**)&ol,  g_ol);
    cudaGetSymbolAddress((void**)&whbase, g_Wh);
    cudaGetSymbolAddress((void**)&wlbase, g_Wl);
    for (int i = 0; i < 6; i++) { wh[i] = whbase + (size_t)i*WSZ; wl[i] = wlbase + (size_t)i*WSZ; }

    cudaFuncSetAttribute(gemm_mma<EPI_NONE>, cudaFuncAttributeMaxDynamicSharedMemorySize, SMEM_BYTES);
    cudaFuncSetAttribute(gemm_mma<EPI_SIG>,  cudaFuncAttributeMaxDynamicSharedMemorySize, SMEM_BYTES);
    cudaFuncSetAttribute(gemm_mma<EPI_USIG>, cudaFuncAttributeMaxDynamicSharedMemorySize, SMEM_BYTES);
    cudaFuncSetAttribute(gemm_mma<EPI_HL>,   cudaFuncAttributeMaxDynamicSharedMemorySize, SMEM_BYTES);

    // launch 0: all 6 weight splits in one kernel (order: Wx, Ww, Wk, Wv, Wr, Wo)
    {
        dim3 cg(WSZ/1024, 6);
        conv_hl_all<<<cg, 256>>>((const float4*)Wx, (const float4*)Ww, (const float4*)Wk,
                                 (const float4*)Wv, (const float4*)Wr, (const float4*)Wo,
                                 (uint2*)whbase, (uint2*)wlbase);
    }

    // launch 1: LayerNorm -> split xn
    ln_kernel<<<MROWS, 256>>>(x, ln_g, ln_b, xnh, xnl);

    dim3 gg(Dm/128, MROWS/128);   // (16, 64)
    // launch 2
    gemm_mma<EPI_HL><<<gg, 256, SMEM_BYTES>>>(xnh, xnl, wh[0], wl[0], nullptr, nullptr, tph, tpl);
    // launch 3
    gemm_mma<EPI_USIG><<<gg, 256, SMEM_BYTES>>>(tph, tpl, wh[1], wl[1], bw, uu, nullptr, nullptr);
    // launch 4
    gemm_mma<EPI_NONE><<<gg, 256, SMEM_BYTES>>>(xnh, xnl, wh[2], wl[2], nullptr, kk, nullptr, nullptr);
    // launch 5  <-- ncu (-s 5 -c 1) captures THIS: plain split-bf16 GEMM
    gemm_mma<EPI_NONE><<<gg, 256, SMEM_BYTES>>>(xnh, xnl, wh[3], wl[3], nullptr, vv, nullptr, nullptr);
    // launch 6
    gemm_mma<EPI_SIG><<<gg, 256, SMEM_BYTES>>>(xnh, xnl, wh[4], wl[4], nullptr, rr, nullptr, nullptr);
    // launch 7
    scan_kernel<<<Bb*Hh, 256>>>(kk, vv, uu, rr, state, oh, ol, sf_out);
    // launch 8
    gemm_mma<EPI_NONE><<<gg, 256, SMEM_BYTES>>>(oh, ol, wh[5], wl[5], nullptr, y_out, nullptr, nullptr);
}

// round 8
// speedup vs baseline: 1.9970x; 1.2342x over previous
#include <cuda_runtime.h>
#include <cuda_bf16.h>
#include <cstdint>
#include <math.h>

#define Dm   2048
#define Bb   4
#define Tt   2048
#define Hh   32
#define HSm  64
#define MROWS 8192
#define YSZ  (MROWS*Dm)
#define WSZ  (Dm*Dm)

typedef unsigned int u32;
typedef __nv_bfloat16 bf16;

// ---------------- static device scratch --------------------------------------
__device__ float g_k[YSZ], g_v[YSZ], g_u[YSZ], g_r[YSZ];
__device__ bf16  g_xnh[YSZ], g_xnl[YSZ], g_tph[YSZ], g_tpl[YSZ], g_oh[YSZ], g_ol[YSZ];
__device__ bf16  g_Wh[6][WSZ], g_Wl[6][WSZ];

// ---------------- helpers ------------------------------------------------------
#define CPA(dst,src)   asm volatile("cp.async.cg.shared.global [%0], [%1], 16;" :: "r"(dst), "l"(src))
#define CPCOMMIT()     asm volatile("cp.async.commit_group;" ::: "memory")
#define CPWAIT(n)      asm volatile("cp.async.wait_group %0;" :: "n"(n) : "memory")

__device__ __forceinline__ u32 s2u(const void* p){
    u32 a; asm("{ .reg .u64 t; cvta.to.shared.u64 t, %1; cvt.u32.u64 %0, t; }" : "=r"(a) : "l"(p)); return a;
}

__device__ __forceinline__ void mma16816(float* c, const u32* a, const u32* b){
    asm volatile("mma.sync.aligned.m16n8k16.row.col.f32.bf16.bf16.f32 "
        "{%0,%1,%2,%3}, {%4,%5,%6,%7}, {%8,%9}, {%0,%1,%2,%3};"
        : "+f"(c[0]), "+f"(c[1]), "+f"(c[2]), "+f"(c[3])
        : "r"(a[0]), "r"(a[1]), "r"(a[2]), "r"(a[3]), "r"(b[0]), "r"(b[1]));
}

union BF2U { __nv_bfloat162 h; u32 u; };

__device__ __forceinline__ void split4(float4 v, uint2& H, uint2& L){
    BF2U h0, h1, l0, l1;
    h0.h = __floats2bfloat162_rn(v.x, v.y);
    h1.h = __floats2bfloat162_rn(v.z, v.w);
    float lx = v.x - __bfloat162float(h0.h.x);
    float ly = v.y - __bfloat162float(h0.h.y);
    float lz = v.z - __bfloat162float(h1.h.x);
    float lw = v.w - __bfloat162float(h1.h.y);
    l0.h = __floats2bfloat162_rn(lx, ly);
    l1.h = __floats2bfloat162_rn(lz, lw);
    H.x = h0.u; H.y = h1.u; L.x = l0.u; L.y = l1.u;
}

// ---------------- weight split (ALL 6 weights in ONE launch) ------------------
__global__ __launch_bounds__(256) void conv_hl_all(
    const float4* __restrict__ s0, const float4* __restrict__ s1,
    const float4* __restrict__ s2, const float4* __restrict__ s3,
    const float4* __restrict__ s4, const float4* __restrict__ s5,
    uint2* __restrict__ dh, uint2* __restrict__ dl)
{
    const int wi = blockIdx.y;
    const float4* src = wi==0?s0 : wi==1?s1 : wi==2?s2 : wi==3?s3 : wi==4?s4 : s5;
    int i = blockIdx.x * 256 + threadIdx.x;
    float4 v = src[i];
    uint2 H, L;
    split4(v, H, L);
    size_t o = (size_t)wi * (WSZ/4) + i;
    dh[o] = H; dl[o] = L;
}

// ---------------- LayerNorm -> hi/lo bf16 -------------------------------------
__global__ __launch_bounds__(256) void ln_kernel(
    const float* __restrict__ x, const float* __restrict__ gam,
    const float* __restrict__ bet, bf16* __restrict__ oh, bf16* __restrict__ ol)
{
    __shared__ float red[18];
    const int row = blockIdx.x;
    const int t = threadIdx.x;
    const float* xr = x + (size_t)row * Dm;

    float4 a0 = *(const float4*)(xr + 4*t);
    float4 a1 = *(const float4*)(xr + 1024 + 4*t);
    float s  = a0.x+a0.y+a0.z+a0.w + a1.x+a1.y+a1.z+a1.w;
    float ss = a0.x*a0.x+a0.y*a0.y+a0.z*a0.z+a0.w*a0.w
             + a1.x*a1.x+a1.y*a1.y+a1.z*a1.z+a1.w*a1.w;
    #pragma unroll
    for (int o = 16; o; o >>= 1) {
        s  += __shfl_xor_sync(0xffffffffu, s,  o);
        ss += __shfl_xor_sync(0xffffffffu, ss, o);
    }
    if ((t & 31) == 0) { red[t>>5] = s; red[8 + (t>>5)] = ss; }
    __syncthreads();
    if (t == 0) {
        float S = 0.f, SS = 0.f;
        #pragma unroll
        for (int i = 0; i < 8; i++) { S += red[i]; SS += red[8+i]; }
        float mu  = S * (1.0f/Dm);
        float var = SS * (1.0f/Dm) - mu*mu;
        red[16] = mu;
        red[17] = rsqrtf(var + 1e-5f);
    }
    __syncthreads();
    const float mu = red[16], rstd = red[17];

    float4 g0 = *(const float4*)(gam + 4*t);
    float4 g1 = *(const float4*)(gam + 1024 + 4*t);
    float4 b0 = *(const float4*)(bet + 4*t);
    float4 b1 = *(const float4*)(bet + 1024 + 4*t);
    float4 r0, r1;
    r0.x = (a0.x - mu)*rstd*g0.x + b0.x;
    r0.y = (a0.y - mu)*rstd*g0.y + b0.y;
    r0.z = (a0.z - mu)*rstd*g0.z + b0.z;
    r0.w = (a0.w - mu)*rstd*g0.w + b0.w;
    r1.x = (a1.x - mu)*rstd*g1.x + b1.x;
    r1.y = (a1.y - mu)*rstd*g1.y + b1.y;
    r1.z = (a1.z - mu)*rstd*g1.z + b1.z;
    r1.w = (a1.w - mu)*rstd*g1.w + b1.w;

    uint2 H, L;
    const size_t o0 = (size_t)row * Dm + 4*t;
    split4(r0, H, L);
    *(uint2*)(oh + o0) = H; *(uint2*)(ol + o0) = L;
    split4(r1, H, L);
    *(uint2*)(oh + o0 + 1024) = H; *(uint2*)(ol + o0 + 1024) = L;
}

// ---------------- split-bf16 mma.sync GEMM: C = A @ W^T -----------------------
// CTA 128x128, BK=32, 8 warps (2x4), warp tile 64x32, double-buffered cp.async.
// smem rows padded to 80B (40 bf16). launch_bounds(256,2) -> 2 CTAs/SM.

#define OFF(tile,buf) ((buf)*40960u + (tile)*10240u)   // AH=0 AL=1 BH=2 BL=3
#define SMEM_BYTES 81920

#define EPI_NONE 0
#define EPI_SIG  1
#define EPI_USIG 2
#define EPI_HL   3

__device__ __forceinline__ void load_tiles(
    u32 sb, int buf, int t,
    const bf16* Ah, const bf16* Al, const bf16* Bh, const bf16* Bl,
    size_t arow, size_t brow, int k0)
{
    #pragma unroll
    for (int p = 0; p < 2; p++) {
        int i = t + p*256;          // 0..511
        int r = i >> 2, c16 = i & 3;
        u32 dst = (u32)(r*80 + c16*16);
        size_t go = (size_t)r*Dm + k0 + c16*8;
        CPA(sb + OFF(0,buf) + dst, (const char*)(Ah + arow + go));
        CPA(sb + OFF(1,buf) + dst, (const char*)(Al + arow + go));
        CPA(sb + OFF(2,buf) + dst, (const char*)(Bh + brow + go));
        CPA(sb + OFF(3,buf) + dst, (const char*)(Bl + brow + go));
    }
}

template<int EPI>
__global__ __launch_bounds__(256, 2) void gemm_mma(
    const bf16* __restrict__ Ah, const bf16* __restrict__ Al,
    const bf16* __restrict__ Bh, const bf16* __restrict__ Bl,
    const float* __restrict__ bias,
    float* __restrict__ C, bf16* __restrict__ Ch, bf16* __restrict__ Cl)
{
    extern __shared__ char sm[];
    const u32 sb = s2u(sm);
    const int t = threadIdx.x;
    const int w = t >> 5, lane = t & 31;
    const int wm = w >> 2, wn = w & 3;       // warp grid 2 (m) x 4 (n)
    const int bn = blockIdx.x, bm = blockIdx.y;

    const size_t arow = (size_t)bm * 128 * Dm;
    const size_t brow = (size_t)bn * 128 * Dm;

    float acc[4][4][4];
    #pragma unroll
    for (int i = 0; i < 4; i++)
        #pragma unroll
        for (int j = 0; j < 4; j++)
            #pragma unroll
            for (int q = 0; q < 4; q++) acc[i][j][q] = 0.f;

    load_tiles(sb, 0, t, Ah, Al, Bh, Bl, arow, brow, 0);
    CPCOMMIT();

    const int lq = lane >> 2;        // 0..7
    const int lr = lane & 3;         // 0..3

    for (int c = 0; c < 64; c++) {
        const int buf = c & 1;
        if (c + 1 < 64) {
            load_tiles(sb, buf ^ 1, t, Ah, Al, Bh, Bl, arow, brow, (c+1)*32);
            CPCOMMIT();
            CPWAIT(1);
        } else {
            CPWAIT(0);
        }
        __syncthreads();

        const bf16* sAh = (const bf16*)(sm + OFF(0,buf));
        const bf16* sAl = (const bf16*)(sm + OFF(1,buf));
        const bf16* sBh = (const bf16*)(sm + OFF(2,buf));
        const bf16* sBl = (const bf16*)(sm + OFF(3,buf));

        #pragma unroll
        for (int ks = 0; ks < 2; ks++) {
            const int kofs = ks*16 + lr*2;
            u32 ah[4][4], al[4][4], bh[4][2], bl[4][2];
            #pragma unroll
            for (int mt = 0; mt < 4; mt++) {
                int r0 = wm*64 + mt*16 + lq;
                ah[mt][0] = *(const u32*)(sAh + r0*40 + kofs);
                ah[mt][1] = *(const u32*)(sAh + (r0+8)*40 + kofs);
                ah[mt][2] = *(const u32*)(sAh + r0*40 + kofs + 8);
                ah[mt][3] = *(const u32*)(sAh + (r0+8)*40 + kofs + 8);
                al[mt][0] = *(const u32*)(sAl + r0*40 + kofs);
                al[mt][1] = *(const u32*)(sAl + (r0+8)*40 + kofs);
                al[mt][2] = *(const u32*)(sAl + r0*40 + kofs + 8);
                al[mt][3] = *(const u32*)(sAl + (r0+8)*40 + kofs + 8);
            }
            #pragma unroll
            for (int nt = 0; nt < 4; nt++) {
                int n0 = wn*32 + nt*8 + lq;
                bh[nt][0] = *(const u32*)(sBh + n0*40 + kofs);
                bh[nt][1] = *(const u32*)(sBh + n0*40 + kofs + 8);
                bl[nt][0] = *(const u32*)(sBl + n0*40 + kofs);
                bl[nt][1] = *(const u32*)(sBl + n0*40 + kofs + 8);
            }
            #pragma unroll
            for (int mt = 0; mt < 4; mt++)
                #pragma unroll
                for (int nt = 0; nt < 4; nt++) {
                    mma16816(acc[mt][nt], ah[mt], bh[nt]);
                    mma16816(acc[mt][nt], ah[mt], bl[nt]);
                    mma16816(acc[mt][nt], al[mt], bh[nt]);
                }
        }
        __syncthreads();
    }

    // ---------------- epilogue ----------------
    #pragma unroll
    for (int mt = 0; mt < 4; mt++) {
        #pragma unroll
        for (int nt = 0; nt < 4; nt++) {
            int row0 = bm*128 + wm*64 + mt*16 + lq;
            int col  = bn*128 + wn*32 + nt*8 + lr*2;
            float v0 = acc[mt][nt][0], v1 = acc[mt][nt][1];
            float v2 = acc[mt][nt][2], v3 = acc[mt][nt][3];
            if (EPI == EPI_SIG) {
                v0 = 1.0f/(1.0f+__expf(-v0)); v1 = 1.0f/(1.0f+__expf(-v1));
                v2 = 1.0f/(1.0f+__expf(-v2)); v3 = 1.0f/(1.0f+__expf(-v3));
            }
            if (EPI == EPI_USIG) {
                float bb0 = __ldg(bias + col), bb1 = __ldg(bias + col + 1);
                v0 = 1.0f/(1.0f+__expf(v0+bb0)); v1 = 1.0f/(1.0f+__expf(v1+bb1));
                v2 = 1.0f/(1.0f+__expf(v2+bb0)); v3 = 1.0f/(1.0f+__expf(v3+bb1));
            }
            if (EPI == EPI_HL) {
                BF2U H0, H1, L0, L1;
                H0.h = __floats2bfloat162_rn(v0, v1);
                H1.h = __floats2bfloat162_rn(v2, v3);
                L0.h = __floats2bfloat162_rn(v0 - __bfloat162float(H0.h.x),
                                             v1 - __bfloat162float(H0.h.y));
                L1.h = __floats2bfloat162_rn(v2 - __bfloat162float(H1.h.x),
                                             v3 - __bfloat162float(H1.h.y));
                *(u32*)(Ch + (size_t)row0*Dm + col)     = H0.u;
                *(u32*)(Ch + (size_t)(row0+8)*Dm + col) = H1.u;
                *(u32*)(Cl + (size_t)row0*Dm + col)     = L0.u;
                *(u32*)(Cl + (size_t)(row0+8)*Dm + col) = L1.u;
            } else {
                *(float2*)(C + (size_t)row0*Dm + col)     = make_float2(v0, v1);
                *(float2*)(C + (size_t)(row0+8)*Dm + col) = make_float2(v2, v3);
            }
        }
    }
}

// ---------------- selective-WKV recurrent scan (cp.async double-buffered) -----
#define CH 8
__global__ __launch_bounds__(256) void scan_kernel(
    const float* __restrict__ kA, const float* __restrict__ vA,
    const float* __restrict__ uA, const float* __restrict__ rA,
    const float* __restrict__ state0, bf16* __restrict__ oh, bf16* __restrict__ ol,
    float* __restrict__ stateF)
{
    const int bh = blockIdx.x;
    const int b  = bh >> 5;
    const int h  = bh & 31;
    const size_t base = (size_t)b * Tt * Dm + (size_t)h * HSm;

    const int t  = threadIdx.x;
    const int ti = t >> 4;
    const int tj = t & 15;

    __shared__ float stg[2][4][CH][64];   // double-buffered k/v/u/r staging
    __shared__ float pS[CH][16][64];

    float S[4][4];
    const float* st0 = state0 + (size_t)bh * 4096;
    #pragma unroll
    for (int ii = 0; ii < 4; ii++) {
        float4 s4 = *(const float4*)(st0 + (ti*4+ii)*64 + tj*4);
        S[ii][0]=s4.x; S[ii][1]=s4.y; S[ii][2]=s4.z; S[ii][3]=s4.w;
    }

    const float* bases[4] = { kA + base, vA + base, uA + base, rA + base };

    // stage chunk c into buffer buf via cp.async (512 x 16B = 8KB)
    const int i0 = t, i1 = t + 256;
    const int a0 = i0 >> 7, s0 = (i0 >> 4) & 7, q0 = i0 & 15;
    const int a1 = i1 >> 7, s1 = (i1 >> 4) & 7, q1 = i1 & 15;

    {
        // prologue: chunk 0
        u32 d0 = s2u(&stg[0][a0][s0][q0*4]);
        u32 d1 = s2u(&stg[0][a1][s1][q1*4]);
        CPA(d0, (const char*)(bases[a0] + (size_t)s0*Dm + q0*4));
        CPA(d1, (const char*)(bases[a1] + (size_t)s1*Dm + q1*4));
        CPCOMMIT();
    }

    for (int c = 0; c < Tt/CH; c++) {
        const int buf = c & 1;
        if (c + 1 < Tt/CH) {
            const size_t nco = (size_t)(c+1) * CH * Dm;
            u32 d0 = s2u(&stg[buf^1][a0][s0][q0*4]);
            u32 d1 = s2u(&stg[buf^1][a1][s1][q1*4]);
            CPA(d0, (const char*)(bases[a0] + nco + (size_t)s0*Dm + q0*4));
            CPA(d1, (const char*)(bases[a1] + nco + (size_t)s1*Dm + q1*4));
            CPCOMMIT();
            CPWAIT(1);
        } else {
            CPWAIT(0);
        }
        __syncthreads();

        #pragma unroll
        for (int s = 0; s < CH; s++) {
            float4 k4 = *(const float4*)(&stg[buf][0][s][ti*4]);
            float4 v4 = *(const float4*)(&stg[buf][1][s][tj*4]);
            float4 u4 = *(const float4*)(&stg[buf][2][s][ti*4]);
            float4 r4 = *(const float4*)(&stg[buf][3][s][ti*4]);
            float kv[4] = {k4.x,k4.y,k4.z,k4.w};
            float uv[4] = {u4.x,u4.y,u4.z,u4.w};
            float rv[4] = {r4.x,r4.y,r4.z,r4.w};
            float vv[4] = {v4.x,v4.y,v4.z,v4.w};
            float p0=0.f,p1=0.f,p2=0.f,p3=0.f;
            #pragma unroll
            for (int ii = 0; ii < 4; ii++) {
                S[ii][0] = fmaf(uv[ii], S[ii][0], kv[ii]*vv[0]);
                S[ii][1] = fmaf(uv[ii], S[ii][1], kv[ii]*vv[1]);
                S[ii][2] = fmaf(uv[ii], S[ii][2], kv[ii]*vv[2]);
                S[ii][3] = fmaf(uv[ii], S[ii][3], kv[ii]*vv[3]);
                p0 = fmaf(rv[ii], S[ii][0], p0);
                p1 = fmaf(rv[ii], S[ii][1], p1);
                p2 = fmaf(rv[ii], S[ii][2], p2);
                p3 = fmaf(rv[ii], S[ii][3], p3);
            }
            *(float4*)(&pS[s][ti][tj*4]) = make_float4(p0,p1,p2,p3);
        }
        __syncthreads();

        const size_t coff = (size_t)c * CH * Dm;
        #pragma unroll
        for (int q = 0; q < 2; q++) {
            int o = t + q*256;
            int s = o >> 6;
            int j = o & 63;
            float sum = 0.f;
            #pragma unroll
            for (int ii = 0; ii < 16; ii++) sum += pS[s][ii][j];
            size_t idx = base + coff + (size_t)s*Dm + j;
            bf16 hv = __float2bfloat16(sum);
            oh[idx] = hv;
            ol[idx] = __float2bfloat16(sum - __bfloat162float(hv));
        }
        __syncthreads();
    }

    float* sf = stateF + (size_t)bh * 4096;
    #pragma unroll
    for (int ii = 0; ii < 4; ii++)
        *(float4*)(sf + (ti*4+ii)*64 + tj*4)
            = make_float4(S[ii][0],S[ii][1],S[ii][2],S[ii][3]);
}

// ---------------- launch ------------------------------------------------------
extern "C" void kernel_launch(void* const* d_in, const int* in_sizes, int n_in,
                              void* d_out, int out_size)
{
    const float* x     = (const float*)d_in[0];
    const float* state = (const float*)d_in[1];
    const float* ln_g  = (const float*)d_in[2];
    const float* ln_b  = (const float*)d_in[3];
    const float* Wx    = (const float*)d_in[4];
    const float* Ww    = (const float*)d_in[5];
    const float* bw    = (const float*)d_in[6];
    const float* Wk    = (const float*)d_in[7];
    const float* Wv    = (const float*)d_in[8];
    const float* Wr    = (const float*)d_in[9];
    const float* Wo    = (const float*)d_in[10];

    float* y_out  = (float*)d_out;
    float* sf_out = (float*)d_out + YSZ;

    float *kk, *vv, *uu, *rr;
    bf16 *xnh, *xnl, *tph, *tpl, *oh, *ol;
    bf16 *wh[6], *wl[6];
    bf16 *whbase, *wlbase;
    cudaGetSymbolAddress((void**)&kk,  g_k);
    cudaGetSymbolAddress((void**)&vv,  g_v);
    cudaGetSymbolAddress((void**)&uu,  g_u);
    cudaGetSymbolAddress((void**)&rr,  g_r);
    cudaGetSymbolAddress((void**)&xnh, g_xnh);
    cudaGetSymbolAddress((void**)&xnl, g_xnl);
    cudaGetSymbolAddress((void**)&tph, g_tph);
    cudaGetSymbolAddress((void**)&tpl, g_tpl);
    cudaGetSymbolAddress((void**)&oh,  g_oh);
    cudaGetSymbolAddress((void**)&ol,  g_ol);
    cudaGetSymbolAddress((void**)&whbase, g_Wh);
    cudaGetSymbolAddress((void**)&wlbase, g_Wl);
    for (int i = 0; i < 6; i++) { wh[i] = whbase + (size_t)i*WSZ; wl[i] = wlbase + (size_t)i*WSZ; }

    cudaFuncSetAttribute(gemm_mma<EPI_NONE>, cudaFuncAttributeMaxDynamicSharedMemorySize, SMEM_BYTES);
    cudaFuncSetAttribute(gemm_mma<EPI_SIG>,  cudaFuncAttributeMaxDynamicSharedMemorySize, SMEM_BYTES);
    cudaFuncSetAttribute(gemm_mma<EPI_USIG>, cudaFuncAttributeMaxDynamicSharedMemorySize, SMEM_BYTES);
    cudaFuncSetAttribute(gemm_mma<EPI_HL>,   cudaFuncAttributeMaxDynamicSharedMemorySize, SMEM_BYTES);

    // launch 0: all 6 weight splits in one kernel
    {
        dim3 cg(WSZ/1024, 6);
        conv_hl_all<<<cg, 256>>>((const float4*)Wx, (const float4*)Ww, (const float4*)Wk,
                                 (const float4*)Wv, (const float4*)Wr, (const float4*)Wo,
                                 (uint2*)whbase, (uint2*)wlbase);
    }

    // launch 1: LayerNorm -> split xn
    ln_kernel<<<MROWS, 256>>>(x, ln_g, ln_b, xnh, xnl);

    dim3 gg(Dm/128, MROWS/128);   // (16, 64)
    // launch 2
    gemm_mma<EPI_HL><<<gg, 256, SMEM_BYTES>>>(xnh, xnl, wh[0], wl[0], nullptr, nullptr, tph, tpl);
    // launch 3
    gemm_mma<EPI_USIG><<<gg, 256, SMEM_BYTES>>>(tph, tpl, wh[1], wl[1], bw, uu, nullptr, nullptr);
    // launch 4
    gemm_mma<EPI_NONE><<<gg, 256, SMEM_BYTES>>>(xnh, xnl, wh[2], wl[2], nullptr, kk, nullptr, nullptr);
    // launch 5  <-- ncu (-s 5 -c 1) captures THIS: plain split-bf16 GEMM
    gemm_mma<EPI_NONE><<<gg, 256, SMEM_BYTES>>>(xnh, xnl, wh[3], wl[3], nullptr, vv, nullptr, nullptr);
    // launch 6
    gemm_mma<EPI_SIG><<<gg, 256, SMEM_BYTES>>>(xnh, xnl, wh[4], wl[4], nullptr, rr, nullptr, nullptr);
    // launch 7
    scan_kernel<<<Bb*Hh, 256>>>(kk, vv, uu, rr, state, oh, ol, sf_out);
    // launch 8
    gemm_mma<EPI_NONE><<<gg, 256, SMEM_BYTES>>>(oh, ol, wh[5], wl[5], nullptr, y_out, nullptr, nullptr);
}

// round 9
// speedup vs baseline: 2.0853x; 1.0442x over previous
#include <cuda_runtime.h>
#include <cuda_bf16.h>
#include <cstdint>
#include <math.h>

#define Dm   2048
#define Bb   4
#define Tt   2048
#define Hh   32
#define HSm  64
#define MROWS 8192
#define YSZ  (MROWS*Dm)
#define WSZ  (Dm*Dm)

typedef unsigned int u32;
typedef __nv_bfloat16 bf16;

// ---------------- static device scratch --------------------------------------
__device__ float g_k[YSZ], g_v[YSZ], g_u[YSZ], g_r[YSZ];
__device__ bf16  g_xnh[YSZ], g_xnl[YSZ], g_tph[YSZ], g_tpl[YSZ], g_oh[YSZ], g_ol[YSZ];
__device__ bf16  g_Wh[6][WSZ], g_Wl[6][WSZ];

// ---------------- helpers ------------------------------------------------------
#define CPA(dst,src)   asm volatile("cp.async.cg.shared.global [%0], [%1], 16;" :: "r"(dst), "l"(src))
#define CPCOMMIT()     asm volatile("cp.async.commit_group;" ::: "memory")
#define CPWAIT(n)      asm volatile("cp.async.wait_group %0;" :: "n"(n) : "memory")

__device__ __forceinline__ u32 s2u(const void* p){
    u32 a; asm("{ .reg .u64 t; cvta.to.shared.u64 t, %1; cvt.u32.u64 %0, t; }" : "=r"(a) : "l"(p)); return a;
}

__device__ __forceinline__ void mma16816(float* c, const u32* a, const u32* b){
    asm volatile("mma.sync.aligned.m16n8k16.row.col.f32.bf16.bf16.f32 "
        "{%0,%1,%2,%3}, {%4,%5,%6,%7}, {%8,%9}, {%0,%1,%2,%3};"
        : "+f"(c[0]), "+f"(c[1]), "+f"(c[2]), "+f"(c[3])
        : "r"(a[0]), "r"(a[1]), "r"(a[2]), "r"(a[3]), "r"(b[0]), "r"(b[1]));
}

union BF2U { __nv_bfloat162 h; u32 u; };

__device__ __forceinline__ void split4(float4 v, uint2& H, uint2& L){
    BF2U h0, h1, l0, l1;
    h0.h = __floats2bfloat162_rn(v.x, v.y);
    h1.h = __floats2bfloat162_rn(v.z, v.w);
    float lx = v.x - __bfloat162float(h0.h.x);
    float ly = v.y - __bfloat162float(h0.h.y);
    float lz = v.z - __bfloat162float(h1.h.x);
    float lw = v.w - __bfloat162float(h1.h.y);
    l0.h = __floats2bfloat162_rn(lx, ly);
    l1.h = __floats2bfloat162_rn(lz, lw);
    H.x = h0.u; H.y = h1.u; L.x = l0.u; L.y = l1.u;
}

// ---------------- weight split (ALL 6 weights in ONE launch) ------------------
__global__ __launch_bounds__(256) void conv_hl_all(
    const float4* __restrict__ s0, const float4* __restrict__ s1,
    const float4* __restrict__ s2, const float4* __restrict__ s3,
    const float4* __restrict__ s4, const float4* __restrict__ s5,
    uint2* __restrict__ dh, uint2* __restrict__ dl)
{
    const int wi = blockIdx.y;
    const float4* src = wi==0?s0 : wi==1?s1 : wi==2?s2 : wi==3?s3 : wi==4?s4 : s5;
    int i = blockIdx.x * 256 + threadIdx.x;
    float4 v = src[i];
    uint2 H, L;
    split4(v, H, L);
    size_t o = (size_t)wi * (WSZ/4) + i;
    dh[o] = H; dl[o] = L;
}

// ---------------- LayerNorm -> hi/lo bf16 -------------------------------------
__global__ __launch_bounds__(256) void ln_kernel(
    const float* __restrict__ x, const float* __restrict__ gam,
    const float* __restrict__ bet, bf16* __restrict__ oh, bf16* __restrict__ ol)
{
    __shared__ float red[18];
    const int row = blockIdx.x;
    const int t = threadIdx.x;
    const float* xr = x + (size_t)row * Dm;

    float4 a0 = *(const float4*)(xr + 4*t);
    float4 a1 = *(const float4*)(xr + 1024 + 4*t);
    float s  = a0.x+a0.y+a0.z+a0.w + a1.x+a1.y+a1.z+a1.w;
    float ss = a0.x*a0.x+a0.y*a0.y+a0.z*a0.z+a0.w*a0.w
             + a1.x*a1.x+a1.y*a1.y+a1.z*a1.z+a1.w*a1.w;
    #pragma unroll
    for (int o = 16; o; o >>= 1) {
        s  += __shfl_xor_sync(0xffffffffu, s,  o);
        ss += __shfl_xor_sync(0xffffffffu, ss, o);
    }
    if ((t & 31) == 0) { red[t>>5] = s; red[8 + (t>>5)] = ss; }
    __syncthreads();
    if (t == 0) {
        float S = 0.f, SS = 0.f;
        #pragma unroll
        for (int i = 0; i < 8; i++) { S += red[i]; SS += red[8+i]; }
        float mu  = S * (1.0f/Dm);
        float var = SS * (1.0f/Dm) - mu*mu;
        red[16] = mu;
        red[17] = rsqrtf(var + 1e-5f);
    }
    __syncthreads();
    const float mu = red[16], rstd = red[17];

    float4 g0 = *(const float4*)(gam + 4*t);
    float4 g1 = *(const float4*)(gam + 1024 + 4*t);
    float4 b0 = *(const float4*)(bet + 4*t);
    float4 b1 = *(const float4*)(bet + 1024 + 4*t);
    float4 r0, r1;
    r0.x = (a0.x - mu)*rstd*g0.x + b0.x;
    r0.y = (a0.y - mu)*rstd*g0.y + b0.y;
    r0.z = (a0.z - mu)*rstd*g0.z + b0.z;
    r0.w = (a0.w - mu)*rstd*g0.w + b0.w;
    r1.x = (a1.x - mu)*rstd*g1.x + b1.x;
    r1.y = (a1.y - mu)*rstd*g1.y + b1.y;
    r1.z = (a1.z - mu)*rstd*g1.z + b1.z;
    r1.w = (a1.w - mu)*rstd*g1.w + b1.w;

    uint2 H, L;
    const size_t o0 = (size_t)row * Dm + 4*t;
    split4(r0, H, L);
    *(uint2*)(oh + o0) = H; *(uint2*)(ol + o0) = L;
    split4(r1, H, L);
    *(uint2*)(oh + o0 + 1024) = H; *(uint2*)(ol + o0 + 1024) = L;
}

// ---------------- split-bf16 mma.sync GEMM core -------------------------------
// CTA 128x128, BK=32, 8 warps (2x4), warp tile 64x32, double-buffered cp.async.
// smem rows padded to 80B (40 bf16) -> conflict-free fragment loads.

#define OFF(tile,buf) ((buf)*40960u + (tile)*10240u)   // AH=0 AL=1 BH=2 BL=3
#define SMEM_BYTES 81920

#define EPI_NONE 0
#define EPI_SIG  1
#define EPI_USIG 2
#define EPI_HL   3

__device__ __forceinline__ void load_tiles(
    u32 sb, int buf, int t,
    const bf16* Ah, const bf16* Al, const bf16* Bh, const bf16* Bl,
    size_t arow, size_t brow, int k0)
{
    #pragma unroll
    for (int p = 0; p < 2; p++) {
        int i = t + p*256;          // 0..511
        int r = i >> 2, c16 = i & 3;
        u32 dst = (u32)(r*80 + c16*16);
        size_t go = (size_t)r*Dm + k0 + c16*8;
        CPA(sb + OFF(0,buf) + dst, (const char*)(Ah + arow + go));
        CPA(sb + OFF(1,buf) + dst, (const char*)(Al + arow + go));
        CPA(sb + OFF(2,buf) + dst, (const char*)(Bh + brow + go));
        CPA(sb + OFF(3,buf) + dst, (const char*)(Bl + brow + go));
    }
}

// interleaved chunk compute: B frags resident, A frags streamed per m-tile
__device__ __forceinline__ void gemm_chunk(
    const bf16* sAh, const bf16* sAl, const bf16* sBh, const bf16* sBl,
    int wm, int wn, int lq, int lr, float (&acc)[4][4][4])
{
    #pragma unroll
    for (int ks = 0; ks < 2; ks++) {
        const int kofs = ks*16 + lr*2;
        u32 bh[4][2], bl[4][2];
        #pragma unroll
        for (int nt = 0; nt < 4; nt++) {
            int n0 = wn*32 + nt*8 + lq;
            bh[nt][0] = *(const u32*)(sBh + n0*40 + kofs);
            bh[nt][1] = *(const u32*)(sBh + n0*40 + kofs + 8);
            bl[nt][0] = *(const u32*)(sBl + n0*40 + kofs);
            bl[nt][1] = *(const u32*)(sBl + n0*40 + kofs + 8);
        }
        #pragma unroll
        for (int mt = 0; mt < 4; mt++) {
            int r0 = wm*64 + mt*16 + lq;
            u32 ah[4], al[4];
            ah[0] = *(const u32*)(sAh + r0*40 + kofs);
            ah[1] = *(const u32*)(sAh + (r0+8)*40 + kofs);
            ah[2] = *(const u32*)(sAh + r0*40 + kofs + 8);
            ah[3] = *(const u32*)(sAh + (r0+8)*40 + kofs + 8);
            al[0] = *(const u32*)(sAl + r0*40 + kofs);
            al[1] = *(const u32*)(sAl + (r0+8)*40 + kofs);
            al[2] = *(const u32*)(sAl + r0*40 + kofs + 8);
            al[3] = *(const u32*)(sAl + (r0+8)*40 + kofs + 8);
            #pragma unroll
            for (int nt = 0; nt < 4; nt++) {
                mma16816(acc[mt][nt], ah, bh[nt]);
                mma16816(acc[mt][nt], ah, bl[nt]);
                mma16816(acc[mt][nt], al, bh[nt]);
            }
        }
    }
}

// epilogue helpers
__device__ __forceinline__ void epi_store_hl(
    bf16* Ch, bf16* Cl, int row0, int col, float v0, float v1, float v2, float v3)
{
    BF2U H0, H1, L0, L1;
    H0.h = __floats2bfloat162_rn(v0, v1);
    H1.h = __floats2bfloat162_rn(v2, v3);
    L0.h = __floats2bfloat162_rn(v0 - __bfloat162float(H0.h.x),
                                 v1 - __bfloat162float(H0.h.y));
    L1.h = __floats2bfloat162_rn(v2 - __bfloat162float(H1.h.x),
                                 v3 - __bfloat162float(H1.h.y));
    *(u32*)(Ch + (size_t)row0*Dm + col)     = H0.u;
    *(u32*)(Ch + (size_t)(row0+8)*Dm + col) = H1.u;
    *(u32*)(Cl + (size_t)row0*Dm + col)     = L0.u;
    *(u32*)(Cl + (size_t)(row0+8)*Dm + col) = L1.u;
}

// ---- batched GEMM over 4 weight sets (shared A), blockIdx.z selects set -----
struct GSet {
    const bf16* Bh; const bf16* Bl;
    float* C; bf16* Ch; bf16* Cl;
    int epi;                       // EPI_NONE / EPI_SIG / EPI_HL
};

__global__ __launch_bounds__(256, 2) void gemm_batch(
    const bf16* __restrict__ Ah, const bf16* __restrict__ Al,
    GSet g0, GSet g1, GSet g2, GSet g3)
{
    extern __shared__ char sm[];
    const u32 sb = s2u(sm);
    const int t = threadIdx.x;
    const int w = t >> 5, lane = t & 31;
    const int wm = w >> 2, wn = w & 3;
    const int bn = blockIdx.x, bm = blockIdx.y, z = blockIdx.z;

    const bf16* Bh = (z==0) ? g0.Bh : (z==1) ? g1.Bh : (z==2) ? g2.Bh : g3.Bh;
    const bf16* Bl = (z==0) ? g0.Bl : (z==1) ? g1.Bl : (z==2) ? g2.Bl : g3.Bl;

    const size_t arow = (size_t)bm * 128 * Dm;
    const size_t brow = (size_t)bn * 128 * Dm;

    float acc[4][4][4];
    #pragma unroll
    for (int i = 0; i < 4; i++)
        #pragma unroll
        for (int j = 0; j < 4; j++)
            #pragma unroll
            for (int q = 0; q < 4; q++) acc[i][j][q] = 0.f;

    load_tiles(sb, 0, t, Ah, Al, Bh, Bl, arow, brow, 0);
    CPCOMMIT();

    const int lq = lane >> 2;
    const int lr = lane & 3;

    for (int c = 0; c < 64; c++) {
        const int buf = c & 1;
        CPWAIT(0);
        __syncthreads();
        if (c + 1 < 64) {
            load_tiles(sb, buf ^ 1, t, Ah, Al, Bh, Bl, arow, brow, (c+1)*32);
            CPCOMMIT();
        }
        gemm_chunk((const bf16*)(sm + OFF(0,buf)), (const bf16*)(sm + OFF(1,buf)),
                   (const bf16*)(sm + OFF(2,buf)), (const bf16*)(sm + OFF(3,buf)),
                   wm, wn, lq, lr, acc);
    }

    // epilogue: resolve output set now (fragments dead, registers free)
    GSet gs = (z==0) ? g0 : (z==1) ? g1 : (z==2) ? g2 : g3;
    #pragma unroll
    for (int mt = 0; mt < 4; mt++) {
        #pragma unroll
        for (int nt = 0; nt < 4; nt++) {
            int row0 = bm*128 + wm*64 + mt*16 + lq;
            int col  = bn*128 + wn*32 + nt*8 + lr*2;
            float v0 = acc[mt][nt][0], v1 = acc[mt][nt][1];
            float v2 = acc[mt][nt][2], v3 = acc[mt][nt][3];
            if (gs.epi == EPI_SIG) {
                v0 = 1.0f/(1.0f+__expf(-v0)); v1 = 1.0f/(1.0f+__expf(-v1));
                v2 = 1.0f/(1.0f+__expf(-v2)); v3 = 1.0f/(1.0f+__expf(-v3));
            }
            if (gs.epi == EPI_HL) {
                epi_store_hl(gs.Ch, gs.Cl, row0, col, v0, v1, v2, v3);
            } else {
                *(float2*)(gs.C + (size_t)row0*Dm + col)     = make_float2(v0, v1);
                *(float2*)(gs.C + (size_t)(row0+8)*Dm + col) = make_float2(v2, v3);
            }
        }
    }
}

// ---- single GEMM (templated epilogue) for Ww (USIG) and Wo (NONE) ------------
template<int EPI>
__global__ __launch_bounds__(256, 2) void gemm_mma(
    const bf16* __restrict__ Ah, const bf16* __restrict__ Al,
    const bf16* __restrict__ Bh, const bf16* __restrict__ Bl,
    const float* __restrict__ bias,
    float* __restrict__ C, bf16* __restrict__ Ch, bf16* __restrict__ Cl)
{
    extern __shared__ char sm[];
    const u32 sb = s2u(sm);
    const int t = threadIdx.x;
    const int w = t >> 5, lane = t & 31;
    const int wm = w >> 2, wn = w & 3;
    const int bn = blockIdx.x, bm = blockIdx.y;

    const size_t arow = (size_t)bm * 128 * Dm;
    const size_t brow = (size_t)bn * 128 * Dm;

    float acc[4][4][4];
    #pragma unroll
    for (int i = 0; i < 4; i++)
        #pragma unroll
        for (int j = 0; j < 4; j++)
            #pragma unroll
            for (int q = 0; q < 4; q++) acc[i][j][q] = 0.f;

    load_tiles(sb, 0, t, Ah, Al, Bh, Bl, arow, brow, 0);
    CPCOMMIT();

    const int lq = lane >> 2;
    const int lr = lane & 3;

    for (int c = 0; c < 64; c++) {
        const int buf = c & 1;
        CPWAIT(0);
        __syncthreads();
        if (c + 1 < 64) {
            load_tiles(sb, buf ^ 1, t, Ah, Al, Bh, Bl, arow, brow, (c+1)*32);
            CPCOMMIT();
        }
        gemm_chunk((const bf16*)(sm + OFF(0,buf)), (const bf16*)(sm + OFF(1,buf)),
                   (const bf16*)(sm + OFF(2,buf)), (const bf16*)(sm + OFF(3,buf)),
                   wm, wn, lq, lr, acc);
    }

    #pragma unroll
    for (int mt = 0; mt < 4; mt++) {
        #pragma unroll
        for (int nt = 0; nt < 4; nt++) {
            int row0 = bm*128 + wm*64 + mt*16 + lq;
            int col  = bn*128 + wn*32 + nt*8 + lr*2;
            float v0 = acc[mt][nt][0], v1 = acc[mt][nt][1];
            float v2 = acc[mt][nt][2], v3 = acc[mt][nt][3];
            if (EPI == EPI_SIG) {
                v0 = 1.0f/(1.0f+__expf(-v0)); v1 = 1.0f/(1.0f+__expf(-v1));
                v2 = 1.0f/(1.0f+__expf(-v2)); v3 = 1.0f/(1.0f+__expf(-v3));
            }
            if (EPI == EPI_USIG) {
                float bb0 = __ldg(bias + col), bb1 = __ldg(bias + col + 1);
                v0 = 1.0f/(1.0f+__expf(v0+bb0)); v1 = 1.0f/(1.0f+__expf(v1+bb1));
                v2 = 1.0f/(1.0f+__expf(v2+bb0)); v3 = 1.0f/(1.0f+__expf(v3+bb1));
            }
            if (EPI == EPI_HL) {
                epi_store_hl(Ch, Cl, row0, col, v0, v1, v2, v3);
            } else {
                *(float2*)(C + (size_t)row0*Dm + col)     = make_float2(v0, v1);
                *(float2*)(C + (size_t)(row0+8)*Dm + col) = make_float2(v2, v3);
            }
        }
    }
}

// ---------------- selective-WKV recurrent scan (cp.async double-buffered) -----
#define CH 8
__global__ __launch_bounds__(256) void scan_kernel(
    const float* __restrict__ kA, const float* __restrict__ vA,
    const float* __restrict__ uA, const float* __restrict__ rA,
    const float* __restrict__ state0, bf16* __restrict__ oh, bf16* __restrict__ ol,
    float* __restrict__ stateF)
{
    const int bh = blockIdx.x;
    const int b  = bh >> 5;
    const int h  = bh & 31;
    const size_t base = (size_t)b * Tt * Dm + (size_t)h * HSm;

    const int t  = threadIdx.x;
    const int ti = t >> 4;
    const int tj = t & 15;

    __shared__ float stg[2][4][CH][64];
    __shared__ float pS[CH][16][64];

    float S[4][4];
    const float* st0 = state0 + (size_t)bh * 4096;
    #pragma unroll
    for (int ii = 0; ii < 4; ii++) {
        float4 s4 = *(const float4*)(st0 + (ti*4+ii)*64 + tj*4);
        S[ii][0]=s4.x; S[ii][1]=s4.y; S[ii][2]=s4.z; S[ii][3]=s4.w;
    }

    const float* bases[4] = { kA + base, vA + base, uA + base, rA + base };

    const int i0 = t, i1 = t + 256;
    const int a0 = i0 >> 7, s0 = (i0 >> 4) & 7, q0 = i0 & 15;
    const int a1 = i1 >> 7, s1 = (i1 >> 4) & 7, q1 = i1 & 15;

    {
        u32 d0 = s2u(&stg[0][a0][s0][q0*4]);
        u32 d1 = s2u(&stg[0][a1][s1][q1*4]);
        CPA(d0, (const char*)(bases[a0] + (size_t)s0*Dm + q0*4));
        CPA(d1, (const char*)(bases[a1] + (size_t)s1*Dm + q1*4));
        CPCOMMIT();
    }

    for (int c = 0; c < Tt/CH; c++) {
        const int buf = c & 1;
        CPWAIT(0);
        __syncthreads();
        if (c + 1 < Tt/CH) {
            const size_t nco = (size_t)(c+1) * CH * Dm;
            u32 d0 = s2u(&stg[buf^1][a0][s0][q0*4]);
            u32 d1 = s2u(&stg[buf^1][a1][s1][q1*4]);
            CPA(d0, (const char*)(bases[a0] + nco + (size_t)s0*Dm + q0*4));
            CPA(d1, (const char*)(bases[a1] + nco + (size_t)s1*Dm + q1*4));
            CPCOMMIT();
        }

        #pragma unroll
        for (int s = 0; s < CH; s++) {
            float4 k4 = *(const float4*)(&stg[buf][0][s][ti*4]);
            float4 v4 = *(const float4*)(&stg[buf][1][s][tj*4]);
            float4 u4 = *(const float4*)(&stg[buf][2][s][ti*4]);
            float4 r4 = *(const float4*)(&stg[buf][3][s][ti*4]);
            float kv[4] = {k4.x,k4.y,k4.z,k4.w};
            float uv[4] = {u4.x,u4.y,u4.z,u4.w};
            float rv[4] = {r4.x,r4.y,r4.z,r4.w};
            float vv[4] = {v4.x,v4.y,v4.z,v4.w};
            float p0=0.f,p1=0.f,p2=0.f,p3=0.f;
            #pragma unroll
            for (int ii = 0; ii < 4; ii++) {
                S[ii][0] = fmaf(uv[ii], S[ii][0], kv[ii]*vv[0]);
                S[ii][1] = fmaf(uv[ii], S[ii][1], kv[ii]*vv[1]);
                S[ii][2] = fmaf(uv[ii], S[ii][2], kv[ii]*vv[2]);
                S[ii][3] = fmaf(uv[ii], S[ii][3], kv[ii]*vv[3]);
                p0 = fmaf(rv[ii], S[ii][0], p0);
                p1 = fmaf(rv[ii], S[ii][1], p1);
                p2 = fmaf(rv[ii], S[ii][2], p2);
                p3 = fmaf(rv[ii], S[ii][3], p3);
            }
            *(float4*)(&pS[s][ti][tj*4]) = make_float4(p0,p1,p2,p3);
        }
        __syncthreads();

        const size_t coff = (size_t)c * CH * Dm;
        #pragma unroll
        for (int q = 0; q < 2; q++) {
            int o = t + q*256;
            int s = o >> 6;
            int j = o & 63;
            float sum = 0.f;
            #pragma unroll
            for (int ii = 0; ii < 16; ii++) sum += pS[s][ii][j];
            size_t idx = base + coff + (size_t)s*Dm + j;
            bf16 hv = __float2bfloat16(sum);
            oh[idx] = hv;
            ol[idx] = __float2bfloat16(sum - __bfloat162float(hv));
        }
        __syncthreads();
    }

    float* sf = stateF + (size_t)bh * 4096;
    #pragma unroll
    for (int ii = 0; ii < 4; ii++)
        *(float4*)(sf + (ti*4+ii)*64 + tj*4)
            = make_float4(S[ii][0],S[ii][1],S[ii][2],S[ii][3]);
}

// ---------------- launch ------------------------------------------------------
extern "C" void kernel_launch(void* const* d_in, const int* in_sizes, int n_in,
                              void* d_out, int out_size)
{
    const float* x     = (const float*)d_in[0];
    const float* state = (const float*)d_in[1];
    const float* ln_g  = (const float*)d_in[2];
    const float* ln_b  = (const float*)d_in[3];
    const float* Wx    = (const float*)d_in[4];
    const float* Ww    = (const float*)d_in[5];
    const float* bw    = (const float*)d_in[6];
    const float* Wk    = (const float*)d_in[7];
    const float* Wv    = (const float*)d_in[8];
    const float* Wr    = (const float*)d_in[9];
    const float* Wo    = (const float*)d_in[10];

    float* y_out  = (float*)d_out;
    float* sf_out = (float*)d_out + YSZ;

    float *kk, *vv, *uu, *rr;
    bf16 *xnh, *xnl, *tph, *tpl, *oh, *ol;
    bf16 *wh[6], *wl[6];
    bf16 *whbase, *wlbase;
    cudaGetSymbolAddress((void**)&kk,  g_k);
    cudaGetSymbolAddress((void**)&vv,  g_v);
    cudaGetSymbolAddress((void**)&uu,  g_u);
    cudaGetSymbolAddress((void**)&rr,  g_r);
    cudaGetSymbolAddress((void**)&xnh, g_xnh);
    cudaGetSymbolAddress((void**)&xnl, g_xnl);
    cudaGetSymbolAddress((void**)&tph, g_tph);
    cudaGetSymbolAddress((void**)&tpl, g_tpl);
    cudaGetSymbolAddress((void**)&oh,  g_oh);
    cudaGetSymbolAddress((void**)&ol,  g_ol);
    cudaGetSymbolAddress((void**)&whbase, g_Wh);
    cudaGetSymbolAddress((void**)&wlbase, g_Wl);
    for (int i = 0; i < 6; i++) { wh[i] = whbase + (size_t)i*WSZ; wl[i] = wlbase + (size_t)i*WSZ; }

    cudaFuncSetAttribute(gemm_batch,         cudaFuncAttributeMaxDynamicSharedMemorySize, SMEM_BYTES);
    cudaFuncSetAttribute(gemm_mma<EPI_USIG>, cudaFuncAttributeMaxDynamicSharedMemorySize, SMEM_BYTES);
    cudaFuncSetAttribute(gemm_mma<EPI_NONE>, cudaFuncAttributeMaxDynamicSharedMemorySize, SMEM_BYTES);

    // launch 0: weight splits (order: Wx, Ww, Wk, Wv, Wr, Wo)
    {
        dim3 cg(WSZ/1024, 6);
        conv_hl_all<<<cg, 256>>>((const float4*)Wx, (const float4*)Ww, (const float4*)Wk,
                                 (const float4*)Wv, (const float4*)Wr, (const float4*)Wo,
                                 (uint2*)whbase, (uint2*)wlbase);
    }

    // launch 1: LayerNorm -> split xn
    ln_kernel<<<MROWS, 256>>>(x, ln_g, ln_b, xnh, xnl);

    // launch 2: batched GEMMs over xn: Wx (HL), Wk, Wv (NONE), Wr (SIG)
    {
        GSet s0 = { wh[0], wl[0], nullptr, tph, tpl, EPI_HL };
        GSet s1 = { wh[2], wl[2], kk, nullptr, nullptr, EPI_NONE };
        GSet s2 = { wh[3], wl[3], vv, nullptr, nullptr, EPI_NONE };
        GSet s3 = { wh[4], wl[4], rr, nullptr, nullptr, EPI_SIG };
        dim3 gg(Dm/128, MROWS/128, 4);   // (16, 64, 4)
        gemm_batch<<<gg, 256, SMEM_BYTES>>>(xnh, xnl, s0, s1, s2, s3);
    }

    dim3 g1(Dm/128, MROWS/128);   // (16, 64)
    // launch 3: u = 1 - sigmoid(tmp @ Ww^T + bw)
    gemm_mma<EPI_USIG><<<g1, 256, SMEM_BYTES>>>(tph, tpl, wh[1], wl[1], bw, uu, nullptr, nullptr);
    // launch 4: scan
    scan_kernel<<<Bb*Hh, 256>>>(kk, vv, uu, rr, state, oh, ol, sf_out);
    // launch 5: y = outs @ Wo^T   <-- ncu (-s 5 -c 1) captures this GEMM
    gemm_mma<EPI_NONE><<<g1, 256, SMEM_BYTES>>>(oh, ol, wh[5], wl[5], nullptr, y_out, nullptr, nullptr);
}

// round 10
// speedup vs baseline: 2.0911x; 1.0028x over previous
#include <cuda_runtime.h>
#include <cuda_bf16.h>
#include <cstdint>
#include <math.h>

#define Dm   2048
#define Bb   4
#define Tt   2048
#define Hh   32
#define HSm  64
#define MROWS 8192
#define YSZ  (MROWS*Dm)
#define WSZ  (Dm*Dm)

typedef unsigned int u32;
typedef __nv_bfloat16 bf16;

// ---------------- static device scratch --------------------------------------
__device__ float g_k[YSZ], g_v[YSZ], g_u[YSZ], g_r[YSZ];
__device__ bf16  g_xnh[YSZ], g_xnl[YSZ], g_tph[YSZ], g_tpl[YSZ], g_oh[YSZ], g_ol[YSZ];
__device__ bf16  g_Wh[6][WSZ], g_Wl[6][WSZ];

// ---------------- helpers ------------------------------------------------------
#define CPA(dst,src)   asm volatile("cp.async.cg.shared.global [%0], [%1], 16;" :: "r"(dst), "l"(src))
#define CPCOMMIT()     asm volatile("cp.async.commit_group;" ::: "memory")
#define CPWAIT(n)      asm volatile("cp.async.wait_group %0;" :: "n"(n) : "memory")

__device__ __forceinline__ u32 s2u(const void* p){
    u32 a; asm("{ .reg .u64 t; cvta.to.shared.u64 t, %1; cvt.u32.u64 %0, t; }" : "=r"(a) : "l"(p)); return a;
}

__device__ __forceinline__ void mma16816(float* c, const u32* a, const u32* b){
    asm volatile("mma.sync.aligned.m16n8k16.row.col.f32.bf16.bf16.f32 "
        "{%0,%1,%2,%3}, {%4,%5,%6,%7}, {%8,%9}, {%0,%1,%2,%3};"
        : "+f"(c[0]), "+f"(c[1]), "+f"(c[2]), "+f"(c[3])
        : "r"(a[0]), "r"(a[1]), "r"(a[2]), "r"(a[3]), "r"(b[0]), "r"(b[1]));
}

union BF2U { __nv_bfloat162 h; u32 u; };

__device__ __forceinline__ void split4(float4 v, uint2& H, uint2& L){
    BF2U h0, h1, l0, l1;
    h0.h = __floats2bfloat162_rn(v.x, v.y);
    h1.h = __floats2bfloat162_rn(v.z, v.w);
    float lx = v.x - __bfloat162float(h0.h.x);
    float ly = v.y - __bfloat162float(h0.h.y);
    float lz = v.z - __bfloat162float(h1.h.x);
    float lw = v.w - __bfloat162float(h1.h.y);
    l0.h = __floats2bfloat162_rn(lx, ly);
    l1.h = __floats2bfloat162_rn(lz, lw);
    H.x = h0.u; H.y = h1.u; L.x = l0.u; L.y = l1.u;
}

// ---------------- weight split (ALL 6 weights in ONE launch) ------------------
__global__ __launch_bounds__(256) void conv_hl_all(
    const float4* __restrict__ s0, const float4* __restrict__ s1,
    const float4* __restrict__ s2, const float4* __restrict__ s3,
    const float4* __restrict__ s4, const float4* __restrict__ s5,
    uint2* __restrict__ dh, uint2* __restrict__ dl)
{
    const int wi = blockIdx.y;
    const float4* src = wi==0?s0 : wi==1?s1 : wi==2?s2 : wi==3?s3 : wi==4?s4 : s5;
    int i = blockIdx.x * 256 + threadIdx.x;
    float4 v = src[i];
    uint2 H, L;
    split4(v, H, L);
    size_t o = (size_t)wi * (WSZ/4) + i;
    dh[o] = H; dl[o] = L;
}

// ---------------- LayerNorm -> hi/lo bf16 -------------------------------------
__global__ __launch_bounds__(256) void ln_kernel(
    const float* __restrict__ x, const float* __restrict__ gam,
    const float* __restrict__ bet, bf16* __restrict__ oh, bf16* __restrict__ ol)
{
    __shared__ float red[18];
    const int row = blockIdx.x;
    const int t = threadIdx.x;
    const float* xr = x + (size_t)row * Dm;

    float4 a0 = *(const float4*)(xr + 4*t);
    float4 a1 = *(const float4*)(xr + 1024 + 4*t);
    float s  = a0.x+a0.y+a0.z+a0.w + a1.x+a1.y+a1.z+a1.w;
    float ss = a0.x*a0.x+a0.y*a0.y+a0.z*a0.z+a0.w*a0.w
             + a1.x*a1.x+a1.y*a1.y+a1.z*a1.z+a1.w*a1.w;
    #pragma unroll
    for (int o = 16; o; o >>= 1) {
        s  += __shfl_xor_sync(0xffffffffu, s,  o);
        ss += __shfl_xor_sync(0xffffffffu, ss, o);
    }
    if ((t & 31) == 0) { red[t>>5] = s; red[8 + (t>>5)] = ss; }
    __syncthreads();
    if (t == 0) {
        float S = 0.f, SS = 0.f;
        #pragma unroll
        for (int i = 0; i < 8; i++) { S += red[i]; SS += red[8+i]; }
        float mu  = S * (1.0f/Dm);
        float var = SS * (1.0f/Dm) - mu*mu;
        red[16] = mu;
        red[17] = rsqrtf(var + 1e-5f);
    }
    __syncthreads();
    const float mu = red[16], rstd = red[17];

    float4 g0 = *(const float4*)(gam + 4*t);
    float4 g1 = *(const float4*)(gam + 1024 + 4*t);
    float4 b0 = *(const float4*)(bet + 4*t);
    float4 b1 = *(const float4*)(bet + 1024 + 4*t);
    float4 r0, r1;
    r0.x = (a0.x - mu)*rstd*g0.x + b0.x;
    r0.y = (a0.y - mu)*rstd*g0.y + b0.y;
    r0.z = (a0.z - mu)*rstd*g0.z + b0.z;
    r0.w = (a0.w - mu)*rstd*g0.w + b0.w;
    r1.x = (a1.x - mu)*rstd*g1.x + b1.x;
    r1.y = (a1.y - mu)*rstd*g1.y + b1.y;
    r1.z = (a1.z - mu)*rstd*g1.z + b1.z;
    r1.w = (a1.w - mu)*rstd*g1.w + b1.w;

    uint2 H, L;
    const size_t o0 = (size_t)row * Dm + 4*t;
    split4(r0, H, L);
    *(uint2*)(oh + o0) = H; *(uint2*)(ol + o0) = L;
    split4(r1, H, L);
    *(uint2*)(oh + o0 + 1024) = H; *(uint2*)(ol + o0 + 1024) = L;
}

// ---------------- split-bf16 mma.sync GEMM core -------------------------------
// CTA 128x128, BK=32, 8 warps (2x4), warp tile 64x32, double-buffered cp.async.
// smem rows padded to 80B (40 bf16) -> conflict-free fragment loads.

#define OFF(tile,buf) ((buf)*40960u + (tile)*10240u)   // AH=0 AL=1 BH=2 BL=3
#define SMEM_BYTES 81920

#define EPI_NONE 0
#define EPI_SIG  1
#define EPI_USIG 2
#define EPI_HL   3

__device__ __forceinline__ void load_tiles(
    u32 sb, int buf, int t,
    const bf16* Ah, const bf16* Al, const bf16* Bh, const bf16* Bl,
    size_t arow, size_t brow, int k0)
{
    #pragma unroll
    for (int p = 0; p < 2; p++) {
        int i = t + p*256;          // 0..511
        int r = i >> 2, c16 = i & 3;
        u32 dst = (u32)(r*80 + c16*16);
        size_t go = (size_t)r*Dm + k0 + c16*8;
        CPA(sb + OFF(0,buf) + dst, (const char*)(Ah + arow + go));
        CPA(sb + OFF(1,buf) + dst, (const char*)(Al + arow + go));
        CPA(sb + OFF(2,buf) + dst, (const char*)(Bh + brow + go));
        CPA(sb + OFF(3,buf) + dst, (const char*)(Bl + brow + go));
    }
}

// interleaved chunk compute: term-major per m-tile -> same-acc RAW distance 4
__device__ __forceinline__ void gemm_chunk(
    const bf16* sAh, const bf16* sAl, const bf16* sBh, const bf16* sBl,
    int wm, int wn, int lq, int lr, float (&acc)[4][4][4])
{
    #pragma unroll
    for (int ks = 0; ks < 2; ks++) {
        const int kofs = ks*16 + lr*2;
        u32 bh[4][2], bl[4][2];
        #pragma unroll
        for (int nt = 0; nt < 4; nt++) {
            int n0 = wn*32 + nt*8 + lq;
            bh[nt][0] = *(const u32*)(sBh + n0*40 + kofs);
            bh[nt][1] = *(const u32*)(sBh + n0*40 + kofs + 8);
            bl[nt][0] = *(const u32*)(sBl + n0*40 + kofs);
            bl[nt][1] = *(const u32*)(sBl + n0*40 + kofs + 8);
        }
        #pragma unroll
        for (int mt = 0; mt < 4; mt++) {
            int r0 = wm*64 + mt*16 + lq;
            u32 ah[4], al[4];
            ah[0] = *(const u32*)(sAh + r0*40 + kofs);
            ah[1] = *(const u32*)(sAh + (r0+8)*40 + kofs);
            ah[2] = *(const u32*)(sAh + r0*40 + kofs + 8);
            ah[3] = *(const u32*)(sAh + (r0+8)*40 + kofs + 8);
            al[0] = *(const u32*)(sAl + r0*40 + kofs);
            al[1] = *(const u32*)(sAl + (r0+8)*40 + kofs);
            al[2] = *(const u32*)(sAl + r0*40 + kofs + 8);
            al[3] = *(const u32*)(sAl + (r0+8)*40 + kofs + 8);
            // term-major: all nt for ah*bh, then ah*bl, then al*bh
            #pragma unroll
            for (int nt = 0; nt < 4; nt++) mma16816(acc[mt][nt], ah, bh[nt]);
            #pragma unroll
            for (int nt = 0; nt < 4; nt++) mma16816(acc[mt][nt], ah, bl[nt]);
            #pragma unroll
            for (int nt = 0; nt < 4; nt++) mma16816(acc[mt][nt], al, bh[nt]);
        }
    }
}

// epilogue helpers
__device__ __forceinline__ void epi_store_hl(
    bf16* Ch, bf16* Cl, int row0, int col, float v0, float v1, float v2, float v3)
{
    BF2U H0, H1, L0, L1;
    H0.h = __floats2bfloat162_rn(v0, v1);
    H1.h = __floats2bfloat162_rn(v2, v3);
    L0.h = __floats2bfloat162_rn(v0 - __bfloat162float(H0.h.x),
                                 v1 - __bfloat162float(H0.h.y));
    L1.h = __floats2bfloat162_rn(v2 - __bfloat162float(H1.h.x),
                                 v3 - __bfloat162float(H1.h.y));
    *(u32*)(Ch + (size_t)row0*Dm + col)     = H0.u;
    *(u32*)(Ch + (size_t)(row0+8)*Dm + col) = H1.u;
    *(u32*)(Cl + (size_t)row0*Dm + col)     = L0.u;
    *(u32*)(Cl + (size_t)(row0+8)*Dm + col) = L1.u;
}

// ---- batched GEMM over 4 weight sets (shared A), blockIdx.z selects set -----
struct GSet {
    const bf16* Bh; const bf16* Bl;
    float* C; bf16* Ch; bf16* Cl;
    int epi;
};

__global__ __launch_bounds__(256, 2) void gemm_batch(
    const bf16* __restrict__ Ah, const bf16* __restrict__ Al,
    GSet g0, GSet g1, GSet g2, GSet g3)
{
    extern __shared__ char sm[];
    const u32 sb = s2u(sm);
    const int t = threadIdx.x;
    const int w = t >> 5, lane = t & 31;
    const int wm = w >> 2, wn = w & 3;
    const int bn = blockIdx.x, bm = blockIdx.y, z = blockIdx.z;

    const bf16* Bh = (z==0) ? g0.Bh : (z==1) ? g1.Bh : (z==2) ? g2.Bh : g3.Bh;
    const bf16* Bl = (z==0) ? g0.Bl : (z==1) ? g1.Bl : (z==2) ? g2.Bl : g3.Bl;

    const size_t arow = (size_t)bm * 128 * Dm;
    const size_t brow = (size_t)bn * 128 * Dm;

    float acc[4][4][4];
    #pragma unroll
    for (int i = 0; i < 4; i++)
        #pragma unroll
        for (int j = 0; j < 4; j++)
            #pragma unroll
            for (int q = 0; q < 4; q++) acc[i][j][q] = 0.f;

    load_tiles(sb, 0, t, Ah, Al, Bh, Bl, arow, brow, 0);
    CPCOMMIT();

    const int lq = lane >> 2;
    const int lr = lane & 3;

    for (int c = 0; c < 64; c++) {
        const int buf = c & 1;
        CPWAIT(0);
        __syncthreads();
        if (c + 1 < 64) {
            load_tiles(sb, buf ^ 1, t, Ah, Al, Bh, Bl, arow, brow, (c+1)*32);
            CPCOMMIT();
        }
        gemm_chunk((const bf16*)(sm + OFF(0,buf)), (const bf16*)(sm + OFF(1,buf)),
                   (const bf16*)(sm + OFF(2,buf)), (const bf16*)(sm + OFF(3,buf)),
                   wm, wn, lq, lr, acc);
    }

    GSet gs = (z==0) ? g0 : (z==1) ? g1 : (z==2) ? g2 : g3;
    #pragma unroll
    for (int mt = 0; mt < 4; mt++) {
        #pragma unroll
        for (int nt = 0; nt < 4; nt++) {
            int row0 = bm*128 + wm*64 + mt*16 + lq;
            int col  = bn*128 + wn*32 + nt*8 + lr*2;
            float v0 = acc[mt][nt][0], v1 = acc[mt][nt][1];
            float v2 = acc[mt][nt][2], v3 = acc[mt][nt][3];
            if (gs.epi == EPI_SIG) {
                v0 = 1.0f/(1.0f+__expf(-v0)); v1 = 1.0f/(1.0f+__expf(-v1));
                v2 = 1.0f/(1.0f+__expf(-v2)); v3 = 1.0f/(1.0f+__expf(-v3));
            }
            if (gs.epi == EPI_HL) {
                epi_store_hl(gs.Ch, gs.Cl, row0, col, v0, v1, v2, v3);
            } else {
                *(float2*)(gs.C + (size_t)row0*Dm + col)     = make_float2(v0, v1);
                *(float2*)(gs.C + (size_t)(row0+8)*Dm + col) = make_float2(v2, v3);
            }
        }
    }
}

// ---- single GEMM (templated epilogue) for Ww (USIG) and Wo (NONE) ------------
template<int EPI>
__global__ __launch_bounds__(256, 2) void gemm_mma(
    const bf16* __restrict__ Ah, const bf16* __restrict__ Al,
    const bf16* __restrict__ Bh, const bf16* __restrict__ Bl,
    const float* __restrict__ bias,
    float* __restrict__ C, bf16* __restrict__ Ch, bf16* __restrict__ Cl)
{
    extern __shared__ char sm[];
    const u32 sb = s2u(sm);
    const int t = threadIdx.x;
    const int w = t >> 5, lane = t & 31;
    const int wm = w >> 2, wn = w & 3;
    const int bn = blockIdx.x, bm = blockIdx.y;

    const size_t arow = (size_t)bm * 128 * Dm;
    const size_t brow = (size_t)bn * 128 * Dm;

    float acc[4][4][4];
    #pragma unroll
    for (int i = 0; i < 4; i++)
        #pragma unroll
        for (int j = 0; j < 4; j++)
            #pragma unroll
            for (int q = 0; q < 4; q++) acc[i][j][q] = 0.f;

    load_tiles(sb, 0, t, Ah, Al, Bh, Bl, arow, brow, 0);
    CPCOMMIT();

    const int lq = lane >> 2;
    const int lr = lane & 3;

    for (int c = 0; c < 64; c++) {
        const int buf = c & 1;
        CPWAIT(0);
        __syncthreads();
        if (c + 1 < 64) {
            load_tiles(sb, buf ^ 1, t, Ah, Al, Bh, Bl, arow, brow, (c+1)*32);
            CPCOMMIT();
        }
        gemm_chunk((const bf16*)(sm + OFF(0,buf)), (const bf16*)(sm + OFF(1,buf)),
                   (const bf16*)(sm + OFF(2,buf)), (const bf16*)(sm + OFF(3,buf)),
                   wm, wn, lq, lr, acc);
    }

    #pragma unroll
    for (int mt = 0; mt < 4; mt++) {
        #pragma unroll
        for (int nt = 0; nt < 4; nt++) {
            int row0 = bm*128 + wm*64 + mt*16 + lq;
            int col  = bn*128 + wn*32 + nt*8 + lr*2;
            float v0 = acc[mt][nt][0], v1 = acc[mt][nt][1];
            float v2 = acc[mt][nt][2], v3 = acc[mt][nt][3];
            if (EPI == EPI_SIG) {
                v0 = 1.0f/(1.0f+__expf(-v0)); v1 = 1.0f/(1.0f+__expf(-v1));
                v2 = 1.0f/(1.0f+__expf(-v2)); v3 = 1.0f/(1.0f+__expf(-v3));
            }
            if (EPI == EPI_USIG) {
                float bb0 = __ldg(bias + col), bb1 = __ldg(bias + col + 1);
                v0 = 1.0f/(1.0f+__expf(v0+bb0)); v1 = 1.0f/(1.0f+__expf(v1+bb1));
                v2 = 1.0f/(1.0f+__expf(v2+bb0)); v3 = 1.0f/(1.0f+__expf(v3+bb1));
            }
            if (EPI == EPI_HL) {
                epi_store_hl(Ch, Cl, row0, col, v0, v1, v2, v3);
            } else {
                *(float2*)(C + (size_t)row0*Dm + col)     = make_float2(v0, v1);
                *(float2*)(C + (size_t)(row0+8)*Dm + col) = make_float2(v2, v3);
            }
        }
    }
}

// ---------------- selective-WKV recurrent scan (cp.async double-buffered) -----
#define CH 8
__global__ __launch_bounds__(256) void scan_kernel(
    const float* __restrict__ kA, const float* __restrict__ vA,
    const float* __restrict__ uA, const float* __restrict__ rA,
    const float* __restrict__ state0, bf16* __restrict__ oh, bf16* __restrict__ ol,
    float* __restrict__ stateF)
{
    const int bh = blockIdx.x;
    const int b  = bh >> 5;
    const int h  = bh & 31;
    const size_t base = (size_t)b * Tt * Dm + (size_t)h * HSm;

    const int t  = threadIdx.x;
    const int ti = t >> 4;
    const int tj = t & 15;

    __shared__ float stg[2][4][CH][64];
    __shared__ float pS[CH][16][64];

    float S[4][4];
    const float* st0 = state0 + (size_t)bh * 4096;
    #pragma unroll
    for (int ii = 0; ii < 4; ii++) {
        float4 s4 = *(const float4*)(st0 + (ti*4+ii)*64 + tj*4);
        S[ii][0]=s4.x; S[ii][1]=s4.y; S[ii][2]=s4.z; S[ii][3]=s4.w;
    }

    const float* bases[4] = { kA + base, vA + base, uA + base, rA + base };

    const int i0 = t, i1 = t + 256;
    const int a0 = i0 >> 7, s0 = (i0 >> 4) & 7, q0 = i0 & 15;
    const int a1 = i1 >> 7, s1 = (i1 >> 4) & 7, q1 = i1 & 15;

    {
        u32 d0 = s2u(&stg[0][a0][s0][q0*4]);
        u32 d1 = s2u(&stg[0][a1][s1][q1*4]);
        CPA(d0, (const char*)(bases[a0] + (size_t)s0*Dm + q0*4));
        CPA(d1, (const char*)(bases[a1] + (size_t)s1*Dm + q1*4));
        CPCOMMIT();
    }

    for (int c = 0; c < Tt/CH; c++) {
        const int buf = c & 1;
        CPWAIT(0);
        __syncthreads();
        if (c + 1 < Tt/CH) {
            const size_t nco = (size_t)(c+1) * CH * Dm;
            u32 d0 = s2u(&stg[buf^1][a0][s0][q0*4]);
            u32 d1 = s2u(&stg[buf^1][a1][s1][q1*4]);
            CPA(d0, (const char*)(bases[a0] + nco + (size_t)s0*Dm + q0*4));
            CPA(d1, (const char*)(bases[a1] + nco + (size_t)s1*Dm + q1*4));
            CPCOMMIT();
        }

        #pragma unroll
        for (int s = 0; s < CH; s++) {
            float4 k4 = *(const float4*)(&stg[buf][0][s][ti*4]);
            float4 v4 = *(const float4*)(&stg[buf][1][s][tj*4]);
            float4 u4 = *(const float4*)(&stg[buf][2][s][ti*4]);
            float4 r4 = *(const float4*)(&stg[buf][3][s][ti*4]);
            float kv[4] = {k4.x,k4.y,k4.z,k4.w};
            float uv[4] = {u4.x,u4.y,u4.z,u4.w};
            float rv[4] = {r4.x,r4.y,r4.z,r4.w};
            float vv[4] = {v4.x,v4.y,v4.z,v4.w};
            float p0=0.f,p1=0.f,p2=0.f,p3=0.f;
            #pragma unroll
            for (int ii = 0; ii < 4; ii++) {
                S[ii][0] = fmaf(uv[ii], S[ii][0], kv[ii]*vv[0]);
                S[ii][1] = fmaf(uv[ii], S[ii][1], kv[ii]*vv[1]);
                S[ii][2] = fmaf(uv[ii], S[ii][2], kv[ii]*vv[2]);
                S[ii][3] = fmaf(uv[ii], S[ii][3], kv[ii]*vv[3]);
                p0 = fmaf(rv[ii], S[ii][0], p0);
                p1 = fmaf(rv[ii], S[ii][1], p1);
                p2 = fmaf(rv[ii], S[ii][2], p2);
                p3 = fmaf(rv[ii], S[ii][3], p3);
            }
            *(float4*)(&pS[s][ti][tj*4]) = make_float4(p0,p1,p2,p3);
        }
        __syncthreads();

        const size_t coff = (size_t)c * CH * Dm;
        #pragma unroll
        for (int q = 0; q < 2; q++) {
            int o = t + q*256;
            int s = o >> 6;
            int j = o & 63;
            float sum = 0.f;
            #pragma unroll
            for (int ii = 0; ii < 16; ii++) sum += pS[s][ii][j];
            size_t idx = base + coff + (size_t)s*Dm + j;
            bf16 hv = __float2bfloat16(sum);
            oh[idx] = hv;
            ol[idx] = __float2bfloat16(sum - __bfloat162float(hv));
        }
        __syncthreads();
    }

    float* sf = stateF + (size_t)bh * 4096;
    #pragma unroll
    for (int ii = 0; ii < 4; ii++)
        *(float4*)(sf + (ti*4+ii)*64 + tj*4)
            = make_float4(S[ii][0],S[ii][1],S[ii][2],S[ii][3]);
}

// ---------------- launch ------------------------------------------------------
extern "C" void kernel_launch(void* const* d_in, const int* in_sizes, int n_in,
                              void* d_out, int out_size)
{
    const float* x     = (const float*)d_in[0];
    const float* state = (const float*)d_in[1];
    const float* ln_g  = (const float*)d_in[2];
    const float* ln_b  = (const float*)d_in[3];
    const float* Wx    = (const float*)d_in[4];
    const float* Ww    = (const float*)d_in[5];
    const float* bw    = (const float*)d_in[6];
    const float* Wk    = (const float*)d_in[7];
    const float* Wv    = (const float*)d_in[8];
    const float* Wr    = (const float*)d_in[9];
    const float* Wo    = (const float*)d_in[10];

    float* y_out  = (float*)d_out;
    float* sf_out = (float*)d_out + YSZ;

    float *kk, *vv, *uu, *rr;
    bf16 *xnh, *xnl, *tph, *tpl, *oh, *ol;
    bf16 *wh[6], *wl[6];
    bf16 *whbase, *wlbase;
    cudaGetSymbolAddress((void**)&kk,  g_k);
    cudaGetSymbolAddress((void**)&vv,  g_v);
    cudaGetSymbolAddress((void**)&uu,  g_u);
    cudaGetSymbolAddress((void**)&rr,  g_r);
    cudaGetSymbolAddress((void**)&xnh, g_xnh);
    cudaGetSymbolAddress((void**)&xnl, g_xnl);
    cudaGetSymbolAddress((void**)&tph, g_tph);
    cudaGetSymbolAddress((void**)&tpl, g_tpl);
    cudaGetSymbolAddress((void**)&oh,  g_oh);
    cudaGetSymbolAddress((void**)&ol,  g_ol);
    cudaGetSymbolAddress((void**)&whbase, g_Wh);
    cudaGetSymbolAddress((void**)&wlbase, g_Wl);
    for (int i = 0; i < 6; i++) { wh[i] = whbase + (size_t)i*WSZ; wl[i] = wlbase + (size_t)i*WSZ; }

    cudaFuncSetAttribute(gemm_batch,         cudaFuncAttributeMaxDynamicSharedMemorySize, SMEM_BYTES);
    cudaFuncSetAttribute(gemm_mma<EPI_USIG>, cudaFuncAttributeMaxDynamicSharedMemorySize, SMEM_BYTES);
    cudaFuncSetAttribute(gemm_mma<EPI_NONE>, cudaFuncAttributeMaxDynamicSharedMemorySize, SMEM_BYTES);

    // launch 0: weight splits (order: Wx, Ww, Wk, Wv, Wr, Wo)
    {
        dim3 cg(WSZ/1024, 6);
        conv_hl_all<<<cg, 256>>>((const float4*)Wx, (const float4*)Ww, (const float4*)Wk,
                                 (const float4*)Wv, (const float4*)Wr, (const float4*)Wo,
                                 (uint2*)whbase, (uint2*)wlbase);
    }

    // launch 1: LayerNorm -> split xn
    ln_kernel<<<MROWS, 256>>>(x, ln_g, ln_b, xnh, xnl);

    // launch 2: batched GEMMs over xn: Wx (HL), Wk, Wv (NONE), Wr (SIG)
    {
        GSet s0 = { wh[0], wl[0], nullptr, tph, tpl, EPI_HL };
        GSet s1 = { wh[2], wl[2], kk, nullptr, nullptr, EPI_NONE };
        GSet s2 = { wh[3], wl[3], vv, nullptr, nullptr, EPI_NONE };
        GSet s3 = { wh[4], wl[4], rr, nullptr, nullptr, EPI_SIG };
        dim3 gg(Dm/128, MROWS/128, 4);   // (16, 64, 4)
        gemm_batch<<<gg, 256, SMEM_BYTES>>>(xnh, xnl, s0, s1, s2, s3);
    }

    dim3 g1(Dm/128, MROWS/128);   // (16, 64)
    // launch 3: u = 1 - sigmoid(tmp @ Ww^T + bw)
    gemm_mma<EPI_USIG><<<g1, 256, SMEM_BYTES>>>(tph, tpl, wh[1], wl[1], bw, uu, nullptr, nullptr);
    // launch 4: scan
    scan_kernel<<<Bb*Hh, 256>>>(kk, vv, uu, rr, state, oh, ol, sf_out);
    // launch 5: y = outs @ Wo^T   <-- ncu (-s 5 -c 1) captures this GEMM
    gemm_mma<EPI_NONE><<<g1, 256, SMEM_BYTES>>>(oh, ol, wh[5], wl[5], nullptr, y_out, nullptr, nullptr);
}